// round 1
// baseline (speedup 1.0000x reference)
#include <cuda_runtime.h>
#include <math.h>
#include <stdint.h>

#define D   256
#define R   8
#define NG  64
#define NMAX 50176          // 392*128, >= 50000
#define EPS 1e-5f

// ---------------- static device scratch (no allocation allowed) ----------------
__device__ float  g_A[(size_t)NMAX * R * D];   // per-(node,relation) edge sums, 411 MB
__device__ float  g_X0[(size_t)NMAX * D];
__device__ float  g_X1[(size_t)NMAX * D];
__device__ float  g_inv[NMAX * R];
__device__ int    g_cnt[NMAX * R];
__device__ double g_stats[2];                  // sum, sumsq for layernorm
__device__ float  g_pool[NG * D];
__device__ int    g_gcnt[NG];

// ---------------- helpers ----------------
__device__ __forceinline__ void red_add_v4(float* addr, float4 v) {
    asm volatile("red.global.add.v4.f32 [%0], {%1,%2,%3,%4};"
                 :: "l"(addr), "f"(v.x), "f"(v.y), "f"(v.z), "f"(v.w) : "memory");
}

// ---------------- edge counting ----------------
__global__ void count_kernel(const int* __restrict__ dst, const int* __restrict__ et, int E) {
    int i = blockIdx.x * blockDim.x + threadIdx.x;
    if (i < E) atomicAdd(&g_cnt[dst[i] * R + et[i]], 1);
}

__global__ void inv_kernel(int n) {
    int i = blockIdx.x * blockDim.x + threadIdx.x;
    if (i < n) g_inv[i] = 1.0f / (float)max(g_cnt[i], 1);
}

// ---------------- scatter: A[dst*R+et] += x[src] ----------------
// block = (64,4): 64 lanes cover 256 floats (float4 each), 4 edges per block
__global__ void scatter_kernel(const float* __restrict__ x,
                               const int* __restrict__ src,
                               const int* __restrict__ dst,
                               const int* __restrict__ et, int E) {
    int e = blockIdx.x * 4 + threadIdx.y;
    if (e >= E) return;
    int s = src[e];
    int seg = dst[e] * R + et[e];
    const float4* xs = (const float4*)(x + (size_t)s * D);
    float4 v = xs[threadIdx.x];
    red_add_v4(g_A + (size_t)seg * D + threadIdx.x * 4, v);
}

// ---------------- fused GEMM: out = relu( Anorm@Wrel + x@Wroot + b + x ) ----------------
// A-matrix row n, column kk in [0,2304): kk<2048 -> g_A[n][kk]*inv_cnt ; else x[n][kk-2048]
// B-matrix: kk<2048 -> Wrel[kk][j] ; else Wroot[kk-2048][j]
#define BM 128
#define BN 128
#define BK 16

__global__ __launch_bounds__(256) void rgcn_gemm(
    const float* __restrict__ Xcur,
    const float* __restrict__ Wrel,   // [R*D, D] row-major
    const float* __restrict__ Wroot,  // [D, D]
    const float* __restrict__ bconv,  // [D]
    float* __restrict__ Xnext, int Nn)
{
    __shared__ float As[BK][BM];
    __shared__ float Bs[BK][BN];
    int tid  = threadIdx.x;
    int row0 = blockIdx.x * BM;
    int col0 = blockIdx.y * BN;

    int arow  = tid >> 1;          // 0..127
    int akoff = (tid & 1) * 8;     // 0 or 8
    int brow  = tid >> 4;          // 0..15
    int bcol  = (tid & 15) * 8;    // 0..120

    int tx = tid & 15, ty = tid >> 4;

    float acc[8][8];
    #pragma unroll
    for (int i = 0; i < 8; i++)
        #pragma unroll
        for (int j = 0; j < 8; j++) acc[i][j] = 0.f;

    for (int k0 = 0; k0 < (R + 1) * D; k0 += BK) {
        // ---- load A tile ----
        {
            int n = row0 + arow;
            float4 v0 = make_float4(0,0,0,0), v1 = make_float4(0,0,0,0);
            if (n < Nn) {
                if (k0 < R * D) {
                    const float* p = g_A + (size_t)n * (R * D) + k0 + akoff;
                    float s = g_inv[n * R + (k0 >> 8)];
                    v0 = *(const float4*)p; v1 = *(const float4*)(p + 4);
                    v0.x *= s; v0.y *= s; v0.z *= s; v0.w *= s;
                    v1.x *= s; v1.y *= s; v1.z *= s; v1.w *= s;
                } else {
                    const float* p = Xcur + (size_t)n * D + (k0 - R * D) + akoff;
                    v0 = *(const float4*)p; v1 = *(const float4*)(p + 4);
                }
            }
            As[akoff + 0][arow] = v0.x; As[akoff + 1][arow] = v0.y;
            As[akoff + 2][arow] = v0.z; As[akoff + 3][arow] = v0.w;
            As[akoff + 4][arow] = v1.x; As[akoff + 5][arow] = v1.y;
            As[akoff + 6][arow] = v1.z; As[akoff + 7][arow] = v1.w;
        }
        // ---- load B tile ----
        {
            const float* Bb = (k0 < R * D) ? (Wrel + (size_t)k0 * D)
                                           : (Wroot + (size_t)(k0 - R * D) * D);
            const float* p = Bb + (size_t)brow * D + col0 + bcol;
            float4 v0 = *(const float4*)p, v1 = *(const float4*)(p + 4);
            *(float4*)&Bs[brow][bcol]     = v0;
            *(float4*)&Bs[brow][bcol + 4] = v1;
        }
        __syncthreads();

        #pragma unroll
        for (int k = 0; k < BK; k++) {
            float a[8], b[8];
            *(float4*)&a[0] = *(const float4*)&As[k][ty * 8];
            *(float4*)&a[4] = *(const float4*)&As[k][ty * 8 + 4];
            *(float4*)&b[0] = *(const float4*)&Bs[k][tx * 8];
            *(float4*)&b[4] = *(const float4*)&Bs[k][tx * 8 + 4];
            #pragma unroll
            for (int i = 0; i < 8; i++)
                #pragma unroll
                for (int j = 0; j < 8; j++)
                    acc[i][j] = fmaf(a[i], b[j], acc[i][j]);
        }
        __syncthreads();
    }

    // ---- epilogue: +bias, +residual(x), relu, store ----
    float4 bv0 = *(const float4*)(bconv + col0 + tx * 8);
    float4 bv1 = *(const float4*)(bconv + col0 + tx * 8 + 4);
    #pragma unroll
    for (int i = 0; i < 8; i++) {
        int n = row0 + ty * 8 + i;
        if (n >= Nn) continue;
        const float4* xp = (const float4*)(Xcur + (size_t)n * D + col0 + tx * 8);
        float4* op       = (float4*)(Xnext + (size_t)n * D + col0 + tx * 8);
        float4 x0 = xp[0], x1 = xp[1];
        float4 o0, o1;
        o0.x = fmaxf(acc[i][0] + bv0.x + x0.x, 0.f);
        o0.y = fmaxf(acc[i][1] + bv0.y + x0.y, 0.f);
        o0.z = fmaxf(acc[i][2] + bv0.z + x0.z, 0.f);
        o0.w = fmaxf(acc[i][3] + bv0.w + x0.w, 0.f);
        o1.x = fmaxf(acc[i][4] + bv1.x + x1.x, 0.f);
        o1.y = fmaxf(acc[i][5] + bv1.y + x1.y, 0.f);
        o1.z = fmaxf(acc[i][6] + bv1.z + x1.z, 0.f);
        o1.w = fmaxf(acc[i][7] + bv1.w + x1.w, 0.f);
        op[0] = o0; op[1] = o1;
    }
}

// ---------------- whole-tensor layernorm ----------------
__global__ void ln_reduce(const float* __restrict__ X, int M) {
    double s = 0.0, q = 0.0;
    for (int i = blockIdx.x * blockDim.x + threadIdx.x; i < M; i += gridDim.x * blockDim.x) {
        float v = X[i];
        s += (double)v;
        q += (double)v * (double)v;
    }
    #pragma unroll
    for (int o = 16; o > 0; o >>= 1) {
        s += __shfl_down_sync(0xffffffffu, s, o);
        q += __shfl_down_sync(0xffffffffu, q, o);
    }
    __shared__ double sh[8], qh[8];
    int lane = threadIdx.x & 31, w = threadIdx.x >> 5;
    if (lane == 0) { sh[w] = s; qh[w] = q; }
    __syncthreads();
    if (w == 0) {
        s = (lane < (blockDim.x >> 5)) ? sh[lane] : 0.0;
        q = (lane < (blockDim.x >> 5)) ? qh[lane] : 0.0;
        #pragma unroll
        for (int o = 4; o > 0; o >>= 1) {
            s += __shfl_down_sync(0xffffffffu, s, o);
            q += __shfl_down_sync(0xffffffffu, q, o);
        }
        if (lane == 0) {
            atomicAdd(&g_stats[0], s);
            atomicAdd(&g_stats[1], q);
        }
    }
}

__global__ void ln_apply(float* __restrict__ X,
                         const float* __restrict__ w,
                         const float* __restrict__ b, int M) {
    int i = blockIdx.x * blockDim.x + threadIdx.x;
    if (i >= M) return;
    double invM = 1.0 / (double)M;
    float mu = (float)(g_stats[0] * invM);
    float var = (float)(g_stats[1] * invM - (g_stats[0] * invM) * (g_stats[0] * invM));
    float sd = sqrtf(fmaxf(var, 0.f));
    float rs = 1.0f / (sd + EPS);
    int j = i & (D - 1);
    X[i] = w[j] * ((X[i] - mu) * rs) + b[j];
}

// ---------------- global mean pool ----------------
__global__ void pool_cnt(const int* __restrict__ batch, int Nn) {
    int i = blockIdx.x * blockDim.x + threadIdx.x;
    if (i < Nn) atomicAdd(&g_gcnt[batch[i]], 1);
}

__global__ void pool_sum(const float* __restrict__ X, const int* __restrict__ batch, int Nn) {
    int idx = blockIdx.x * blockDim.x + threadIdx.x;
    if (idx >= Nn * (D / 4)) return;
    int n = idx >> 6, c = idx & 63;
    float4 v = ((const float4*)X)[(size_t)n * (D / 4) + c];
    red_add_v4(g_pool + batch[n] * D + c * 4, v);
}

// ---------------- MLP head: one block per graph ----------------
__global__ void head_kernel(const float* __restrict__ W1, const float* __restrict__ b1,
                            const float* __restrict__ W2, const float* __restrict__ b2,
                            const float* __restrict__ W3, const float* __restrict__ b3,
                            float* __restrict__ out) {
    __shared__ float g[D], h1[D], h2[D];
    int bg = blockIdx.x, j = threadIdx.x;
    float c = fmaxf((float)g_gcnt[bg], 1.f);
    g[j] = g_pool[bg * D + j] / c;
    __syncthreads();
    float acc = b1[j];
    for (int k = 0; k < D; k++) acc = fmaf(g[k], W1[k * D + j], acc);
    h1[j] = fmaxf(acc, 0.f);
    __syncthreads();
    acc = b2[j];
    for (int k = 0; k < D; k++) acc = fmaf(h1[k], W2[k * D + j], acc);
    h2[j] = fmaxf(acc, 0.f);
    __syncthreads();
    if (j < 4) {
        acc = b3[j];
        for (int k = 0; k < D; k++) acc = fmaf(h2[k], W3[k * 4 + j], acc);
        out[bg * 4 + j] = acc;
    }
}

// ---------------- launch ----------------
extern "C" void kernel_launch(void* const* d_in, const int* in_sizes, int n_in,
                              void* d_out, int out_size) {
    const float* x      = (const float*)d_in[0];
    const int*   ei     = (const int*)d_in[1];
    const int*   et     = (const int*)d_in[2];
    const int*   batch  = (const int*)d_in[3];
    const float* W_rel  = (const float*)d_in[4];
    const float* W_root = (const float*)d_in[5];
    const float* b_conv = (const float*)d_in[6];
    const float* ln_w   = (const float*)d_in[7];
    const float* ln_b   = (const float*)d_in[8];
    const float* W1 = (const float*)d_in[9];
    const float* b1 = (const float*)d_in[10];
    const float* W2 = (const float*)d_in[11];
    const float* b2 = (const float*)d_in[12];
    const float* W3 = (const float*)d_in[13];
    const float* b3 = (const float*)d_in[14];

    int E  = in_sizes[1] / 2;
    int Nn = in_sizes[0] / D;
    const int* src = ei;
    const int* dst = ei + E;

    void *pA, *pX0, *pX1, *pCnt, *pStats, *pPool, *pGcnt;
    cudaGetSymbolAddress(&pA, g_A);
    cudaGetSymbolAddress(&pX0, g_X0);
    cudaGetSymbolAddress(&pX1, g_X1);
    cudaGetSymbolAddress(&pCnt, g_cnt);
    cudaGetSymbolAddress(&pStats, g_stats);
    cudaGetSymbolAddress(&pPool, g_pool);
    cudaGetSymbolAddress(&pGcnt, g_gcnt);

    // edge counts (same for all layers)
    cudaMemsetAsync(pCnt, 0, (size_t)Nn * R * sizeof(int));
    count_kernel<<<(E + 255) / 256, 256>>>(dst, et, E);
    inv_kernel<<<(Nn * R + 255) / 256, 256>>>(Nn * R);

    const float* cur = x;
    float* bufs[2] = { (float*)pX0, (float*)pX1 };

    for (int l = 0; l < 3; l++) {
        cudaMemsetAsync(pA, 0, (size_t)Nn * R * D * sizeof(float));
        scatter_kernel<<<(E + 3) / 4, dim3(64, 4)>>>(cur, src, dst, et, E);
        float* nxt = bufs[l & 1];
        dim3 grid((Nn + BM - 1) / BM, D / BN);
        rgcn_gemm<<<grid, 256>>>(cur,
                                 W_rel + (size_t)l * R * D * D,
                                 W_root + (size_t)l * D * D,
                                 b_conv + l * D, nxt, Nn);
        if (l < 2) {
            cudaMemsetAsync(pStats, 0, 2 * sizeof(double));
            ln_reduce<<<1024, 256>>>(nxt, Nn * D);
            ln_apply<<<(Nn * D + 255) / 256, 256>>>(nxt, ln_w + l * D, ln_b + l * D, Nn * D);
        }
        cur = nxt;
    }

    cudaMemsetAsync(pPool, 0, NG * D * sizeof(float));
    cudaMemsetAsync(pGcnt, 0, NG * sizeof(int));
    pool_cnt<<<(Nn + 255) / 256, 256>>>(batch, Nn);
    pool_sum<<<(Nn * (D / 4) + 255) / 256, 256>>>(cur, batch, Nn);
    head_kernel<<<NG, D>>>(W1, b1, W2, b2, W3, b3, (float*)d_out);
}

// round 3
// speedup vs baseline: 1.3750x; 1.3750x over previous
#include <cuda_runtime.h>
#include <cuda_bf16.h>
#include <math.h>
#include <stdint.h>

#define D    256
#define R    8
#define NG   64
#define NMAX 50176          // 392*128
#define EPS  1e-5f
#define KTOT 2304           // (R+1)*D
#define NST  72             // KTOT / 32
#define BM   128
#define BN   128

// smem layout (bf16, row stride 40 elements = 80B, conflict-free for ldmatrix)
#define LDA   40
#define OAHI  0
#define OALO  10240
#define OBHI  20480
#define OBLO  30720
#define STG   40960
#define SMEM_TOTAL (2 * STG)

// ---------------- static device scratch ----------------
__device__ float  g_A[(size_t)NMAX * R * D];
__device__ float  g_X0[(size_t)NMAX * D];
__device__ float  g_X1[(size_t)NMAX * D];
__device__ float  g_inv[NMAX * R];
__device__ int    g_cnt[NMAX * R];
__device__ double g_stats[2];
__device__ float  g_pool[NG * D];
__device__ int    g_gcnt[NG];
__device__ __nv_bfloat16 g_Bhi[(size_t)D * KTOT];   // [j][k] K-major
__device__ __nv_bfloat16 g_Blo[(size_t)D * KTOT];

// ---------------- helpers ----------------
__device__ __forceinline__ uint32_t smem_u32(const void* p) {
    return (uint32_t)__cvta_generic_to_shared((void*)p);
}
__device__ __forceinline__ void red_add_v4(float* addr, float4 v) {
    asm volatile("red.global.add.v4.f32 [%0], {%1,%2,%3,%4};"
                 :: "l"(addr), "f"(v.x), "f"(v.y), "f"(v.z), "f"(v.w) : "memory");
}
__device__ __forceinline__ void ldsm4(uint32_t (&r)[4], uint32_t addr) {
    asm volatile("ldmatrix.sync.aligned.m8n8.x4.shared.b16 {%0,%1,%2,%3}, [%4];"
                 : "=r"(r[0]), "=r"(r[1]), "=r"(r[2]), "=r"(r[3]) : "r"(addr));
}
__device__ __forceinline__ void mma16816(float (&d)[4], const uint32_t (&a)[4],
                                         uint32_t b0, uint32_t b1) {
    asm volatile(
        "mma.sync.aligned.m16n8k16.row.col.f32.bf16.bf16.f32 "
        "{%0,%1,%2,%3}, {%4,%5,%6,%7}, {%8,%9}, {%0,%1,%2,%3};"
        : "+f"(d[0]), "+f"(d[1]), "+f"(d[2]), "+f"(d[3])
        : "r"(a[0]), "r"(a[1]), "r"(a[2]), "r"(a[3]), "r"(b0), "r"(b1));
}

// ---------------- edge counting ----------------
__global__ void count_kernel(const int* __restrict__ dst, const int* __restrict__ et, int E) {
    int i = blockIdx.x * blockDim.x + threadIdx.x;
    if (i < E) atomicAdd(&g_cnt[dst[i] * R + et[i]], 1);
}
__global__ void inv_kernel(int n) {
    int i = blockIdx.x * blockDim.x + threadIdx.x;
    if (i < n) g_inv[i] = 1.0f / (float)max(g_cnt[i], 1);
}

// ---------------- scatter: A[dst*R+et] += x[src] ----------------
__global__ void scatter_kernel(const float* __restrict__ x,
                               const int* __restrict__ src,
                               const int* __restrict__ dst,
                               const int* __restrict__ et, int E) {
    int e = blockIdx.x * 4 + threadIdx.y;
    if (e >= E) return;
    int s = src[e];
    int seg = dst[e] * R + et[e];
    const float4* xs = (const float4*)(x + (size_t)s * D);
    float4 v = xs[threadIdx.x];
    red_add_v4(g_A + (size_t)seg * D + threadIdx.x * 4, v);
}

// ---------------- weight prep: transpose + bf16 hi/lo split ----------------
__global__ void prep_B(const float* __restrict__ Wrel, const float* __restrict__ Wroot) {
    __shared__ float s[32][33];
    int k0 = blockIdx.x * 32, j0 = blockIdx.y * 32;
    for (int i = threadIdx.y; i < 32; i += 8) {
        int k = k0 + i;
        const float* row = (k < R * D) ? (Wrel + (size_t)k * D)
                                       : (Wroot + (size_t)(k - R * D) * D);
        s[i][threadIdx.x] = row[j0 + threadIdx.x];
    }
    __syncthreads();
    for (int i = threadIdx.y; i < 32; i += 8) {
        int j = j0 + i;
        float v = s[threadIdx.x][i];
        __nv_bfloat16 hi = __float2bfloat16(v);
        float lo = v - __bfloat162float(hi);
        g_Bhi[(size_t)j * KTOT + k0 + threadIdx.x] = hi;
        g_Blo[(size_t)j * KTOT + k0 + threadIdx.x] = __float2bfloat16(lo);
    }
}

// ---------------- HMMA GEMM: out = relu([A*inv | x] @ Wcat + b + x) ----------------
__global__ __launch_bounds__(256) void rgcn_hmma(
    const float* __restrict__ Xcur,
    const float* __restrict__ bconv,
    float* __restrict__ Xnext, int Nn)
{
    extern __shared__ char sm[];
    uint32_t sbase = smem_u32(sm);
    int tid = threadIdx.x, lane = tid & 31, wid = tid >> 5;
    int wm = wid & 1, wn = wid >> 1;          // warp tile: rows wm*64, cols wn*32
    int row0 = blockIdx.x * BM, col0 = blockIdx.y * BN;

    float acc[4][4][4];
    #pragma unroll
    for (int i = 0; i < 4; i++)
        #pragma unroll
        for (int j = 0; j < 4; j++)
            #pragma unroll
            for (int q = 0; q < 4; q++) acc[i][j][q] = 0.f;

    // staging mapping: 2 threads per row; each handles 16 k-values
    int ar = tid >> 1, aseg = tid & 1;
    int an = row0 + ar;
    bool aval = an < Nn;
    int bj = col0 + ar;

    float av[16];
    uint4 bh0, bh1, bl0, bl1;

    auto gload = [&](int kt) {
        int k = kt * 32 + aseg * 16;
        if (aval) {
            const float* p;
            float s = 1.0f;
            if (k < R * D) {
                p = g_A + (size_t)an * (R * D) + k;
                s = g_inv[an * R + (kt >> 3)];
            } else {
                p = Xcur + (size_t)an * D + (k - R * D);
            }
            #pragma unroll
            for (int q = 0; q < 4; q++) {
                float4 v = *(const float4*)(p + q * 4);
                av[q * 4 + 0] = v.x * s; av[q * 4 + 1] = v.y * s;
                av[q * 4 + 2] = v.z * s; av[q * 4 + 3] = v.w * s;
            }
        } else {
            #pragma unroll
            for (int q = 0; q < 16; q++) av[q] = 0.f;
        }
        size_t gb = (size_t)bj * KTOT + kt * 32 + aseg * 16;
        bh0 = *(const uint4*)(g_Bhi + gb);
        bh1 = *(const uint4*)(g_Bhi + gb + 8);
        bl0 = *(const uint4*)(g_Blo + gb);
        bl1 = *(const uint4*)(g_Blo + gb + 8);
    };

    auto sstore = [&](int buf) {
        char* st = sm + buf * STG;
        uint32_t hw[8], lw[8];
        #pragma unroll
        for (int p = 0; p < 8; p++) {
            float v0 = av[2 * p], v1 = av[2 * p + 1];
            __nv_bfloat16 h0 = __float2bfloat16(v0);
            __nv_bfloat16 h1 = __float2bfloat16(v1);
            float l0 = v0 - __bfloat162float(h0);
            float l1 = v1 - __bfloat162float(h1);
            __nv_bfloat162 hh = __halves2bfloat162(h0, h1);
            __nv_bfloat162 ll = __floats2bfloat162_rn(l0, l1);
            hw[p] = *reinterpret_cast<uint32_t*>(&hh);
            lw[p] = *reinterpret_cast<uint32_t*>(&ll);
        }
        uint32_t byte = (uint32_t)(ar * (LDA * 2) + aseg * 32);
        *(uint4*)(st + OAHI + byte)      = make_uint4(hw[0], hw[1], hw[2], hw[3]);
        *(uint4*)(st + OAHI + byte + 16) = make_uint4(hw[4], hw[5], hw[6], hw[7]);
        *(uint4*)(st + OALO + byte)      = make_uint4(lw[0], lw[1], lw[2], lw[3]);
        *(uint4*)(st + OALO + byte + 16) = make_uint4(lw[4], lw[5], lw[6], lw[7]);
        *(uint4*)(st + OBHI + byte)      = bh0;
        *(uint4*)(st + OBHI + byte + 16) = bh1;
        *(uint4*)(st + OBLO + byte)      = bl0;
        *(uint4*)(st + OBLO + byte + 16) = bl1;
    };

    // prologue
    gload(0);
    sstore(0);
    __syncthreads();

    uint32_t a_row_off = (uint32_t)((wm * 64 + (lane & 15)) * (LDA * 2));
    uint32_t b_row_off = (uint32_t)((wn * 32 + (lane & 15)) * (LDA * 2));
    uint32_t k_half = (uint32_t)((lane >> 4) * 16);

    #pragma unroll 1
    for (int kt = 0; kt < NST; kt++) {
        if (kt + 1 < NST) gload(kt + 1);

        uint32_t sb = sbase + (kt & 1) * STG;
        #pragma unroll
        for (int ks = 0; ks < 2; ks++) {
            uint32_t koff = ks * 32 + k_half;
            uint32_t ah[4][4], al[4][4];
            #pragma unroll
            for (int mi = 0; mi < 4; mi++) {
                uint32_t ad = sb + a_row_off + mi * 16 * (LDA * 2) + koff;
                ldsm4(ah[mi], ad + OAHI);
                ldsm4(al[mi], ad + OALO);
            }
            uint32_t bhf[2][4], blf[2][4];
            #pragma unroll
            for (int nj2 = 0; nj2 < 2; nj2++) {
                uint32_t bd = sb + b_row_off + nj2 * 16 * (LDA * 2) + koff;
                ldsm4(bhf[nj2], bd + OBHI);
                ldsm4(blf[nj2], bd + OBLO);
            }
            #pragma unroll
            for (int mi = 0; mi < 4; mi++) {
                #pragma unroll
                for (int nj2 = 0; nj2 < 2; nj2++) {
                    mma16816(acc[mi][nj2 * 2],     ah[mi], bhf[nj2][0], bhf[nj2][2]);
                    mma16816(acc[mi][nj2 * 2],     ah[mi], blf[nj2][0], blf[nj2][2]);
                    mma16816(acc[mi][nj2 * 2],     al[mi], bhf[nj2][0], bhf[nj2][2]);
                    mma16816(acc[mi][nj2 * 2 + 1], ah[mi], bhf[nj2][1], bhf[nj2][3]);
                    mma16816(acc[mi][nj2 * 2 + 1], ah[mi], blf[nj2][1], blf[nj2][3]);
                    mma16816(acc[mi][nj2 * 2 + 1], al[mi], bhf[nj2][1], bhf[nj2][3]);
                }
            }
        }
        if (kt + 1 < NST) sstore((kt + 1) & 1);
        __syncthreads();
    }

    // ---- epilogue: bias + residual + relu ----
    int gr = lane >> 2, gc = lane & 3;
    #pragma unroll
    for (int mi = 0; mi < 4; mi++) {
        #pragma unroll
        for (int half = 0; half < 2; half++) {
            int n = row0 + wm * 64 + mi * 16 + gr + half * 8;
            if (n >= Nn) continue;
            #pragma unroll
            for (int nj = 0; nj < 4; nj++) {
                int col = col0 + wn * 32 + nj * 8 + gc * 2;
                float2 xv = *(const float2*)(Xcur + (size_t)n * D + col);
                float2 bv = *(const float2*)(bconv + col);
                float c0 = acc[mi][nj][half * 2 + 0];
                float c1 = acc[mi][nj][half * 2 + 1];
                float2 o;
                o.x = fmaxf(c0 + bv.x + xv.x, 0.f);
                o.y = fmaxf(c1 + bv.y + xv.y, 0.f);
                *(float2*)(Xnext + (size_t)n * D + col) = o;
            }
        }
    }
}

// ---------------- whole-tensor layernorm ----------------
__global__ void ln_reduce(const float* __restrict__ X, int M) {
    double s = 0.0, q = 0.0;
    for (int i = blockIdx.x * blockDim.x + threadIdx.x; i < M; i += gridDim.x * blockDim.x) {
        float v = X[i];
        s += (double)v;
        q += (double)v * (double)v;
    }
    #pragma unroll
    for (int o = 16; o > 0; o >>= 1) {
        s += __shfl_down_sync(0xffffffffu, s, o);
        q += __shfl_down_sync(0xffffffffu, q, o);
    }
    __shared__ double sh[8], qh[8];
    int lane = threadIdx.x & 31, w = threadIdx.x >> 5;
    if (lane == 0) { sh[w] = s; qh[w] = q; }
    __syncthreads();
    if (w == 0) {
        s = (lane < (blockDim.x >> 5)) ? sh[lane] : 0.0;
        q = (lane < (blockDim.x >> 5)) ? qh[lane] : 0.0;
        #pragma unroll
        for (int o = 4; o > 0; o >>= 1) {
            s += __shfl_down_sync(0xffffffffu, s, o);
            q += __shfl_down_sync(0xffffffffu, q, o);
        }
        if (lane == 0) {
            atomicAdd(&g_stats[0], s);
            atomicAdd(&g_stats[1], q);
        }
    }
}

__global__ void ln_apply(float* __restrict__ X,
                         const float* __restrict__ w,
                         const float* __restrict__ b, int M) {
    int i = blockIdx.x * blockDim.x + threadIdx.x;
    if (i >= M) return;
    double invM = 1.0 / (double)M;
    float mu = (float)(g_stats[0] * invM);
    float var = (float)(g_stats[1] * invM - (g_stats[0] * invM) * (g_stats[0] * invM));
    float sd = sqrtf(fmaxf(var, 0.f));
    float rs = 1.0f / (sd + EPS);
    int j = i & (D - 1);
    X[i] = w[j] * ((X[i] - mu) * rs) + b[j];
}

// ---------------- global mean pool ----------------
__global__ void pool_cnt(const int* __restrict__ batch, int Nn) {
    int i = blockIdx.x * blockDim.x + threadIdx.x;
    if (i < Nn) atomicAdd(&g_gcnt[batch[i]], 1);
}
__global__ void pool_sum(const float* __restrict__ X, const int* __restrict__ batch, int Nn) {
    int idx = blockIdx.x * blockDim.x + threadIdx.x;
    if (idx >= Nn * (D / 4)) return;
    int n = idx >> 6, c = idx & 63;
    float4 v = ((const float4*)X)[(size_t)n * (D / 4) + c];
    red_add_v4(g_pool + batch[n] * D + c * 4, v);
}

// ---------------- MLP head ----------------
__global__ void head_kernel(const float* __restrict__ W1, const float* __restrict__ b1,
                            const float* __restrict__ W2, const float* __restrict__ b2,
                            const float* __restrict__ W3, const float* __restrict__ b3,
                            float* __restrict__ out) {
    __shared__ float g[D], h1[D], h2[D];
    int bg = blockIdx.x, j = threadIdx.x;
    float c = fmaxf((float)g_gcnt[bg], 1.f);
    g[j] = g_pool[bg * D + j] / c;
    __syncthreads();
    float acc = b1[j];
    for (int k = 0; k < D; k++) acc = fmaf(g[k], W1[k * D + j], acc);
    h1[j] = fmaxf(acc, 0.f);
    __syncthreads();
    acc = b2[j];
    for (int k = 0; k < D; k++) acc = fmaf(h1[k], W2[k * D + j], acc);
    h2[j] = fmaxf(acc, 0.f);
    __syncthreads();
    if (j < 4) {
        acc = b3[j];
        for (int k = 0; k < D; k++) acc = fmaf(h2[k], W3[k * 4 + j], acc);
        out[bg * 4 + j] = acc;
    }
}

// ---------------- launch ----------------
extern "C" void kernel_launch(void* const* d_in, const int* in_sizes, int n_in,
                              void* d_out, int out_size) {
    const float* x      = (const float*)d_in[0];
    const int*   ei     = (const int*)d_in[1];
    const int*   et     = (const int*)d_in[2];
    const int*   batch  = (const int*)d_in[3];
    const float* W_rel  = (const float*)d_in[4];
    const float* W_root = (const float*)d_in[5];
    const float* b_conv = (const float*)d_in[6];
    const float* ln_w   = (const float*)d_in[7];
    const float* ln_b   = (const float*)d_in[8];
    const float* W1 = (const float*)d_in[9];
    const float* b1 = (const float*)d_in[10];
    const float* W2 = (const float*)d_in[11];
    const float* b2 = (const float*)d_in[12];
    const float* W3 = (const float*)d_in[13];
    const float* b3 = (const float*)d_in[14];

    int E  = in_sizes[1] / 2;
    int Nn = in_sizes[0] / D;
    const int* src = ei;
    const int* dst = ei + E;

    cudaFuncSetAttribute(rgcn_hmma, cudaFuncAttributeMaxDynamicSharedMemorySize, SMEM_TOTAL);

    void *pA, *pX0, *pX1, *pCnt, *pStats, *pPool, *pGcnt;
    cudaGetSymbolAddress(&pA, g_A);
    cudaGetSymbolAddress(&pX0, g_X0);
    cudaGetSymbolAddress(&pX1, g_X1);
    cudaGetSymbolAddress(&pCnt, g_cnt);
    cudaGetSymbolAddress(&pStats, g_stats);
    cudaGetSymbolAddress(&pPool, g_pool);
    cudaGetSymbolAddress(&pGcnt, g_gcnt);

    cudaMemsetAsync(pCnt, 0, (size_t)Nn * R * sizeof(int));
    count_kernel<<<(E + 255) / 256, 256>>>(dst, et, E);
    inv_kernel<<<(Nn * R + 255) / 256, 256>>>(Nn * R);

    const float* cur = x;
    float* bufs[2] = { (float*)pX0, (float*)pX1 };

    for (int l = 0; l < 3; l++) {
        cudaMemsetAsync(pA, 0, (size_t)Nn * R * D * sizeof(float));
        scatter_kernel<<<(E + 3) / 4, dim3(64, 4)>>>(cur, src, dst, et, E);
        prep_B<<<dim3(KTOT / 32, D / 32), dim3(32, 8)>>>(
            W_rel + (size_t)l * R * D * D, W_root + (size_t)l * D * D);
        float* nxt = bufs[l & 1];
        rgcn_hmma<<<dim3(NMAX / BM, D / BN), 256, SMEM_TOTAL>>>(
            cur, b_conv + l * D, nxt, Nn);
        if (l < 2) {
            cudaMemsetAsync(pStats, 0, 2 * sizeof(double));
            ln_reduce<<<1024, 256>>>(nxt, Nn * D);
            ln_apply<<<(Nn * D + 255) / 256, 256>>>(nxt, ln_w + l * D, ln_b + l * D, Nn * D);
        }
        cur = nxt;
    }

    cudaMemsetAsync(pPool, 0, NG * D * sizeof(float));
    cudaMemsetAsync(pGcnt, 0, NG * sizeof(int));
    pool_cnt<<<(Nn + 255) / 256, 256>>>(batch, Nn);
    pool_sum<<<(Nn * (D / 4) + 255) / 256, 256>>>(cur, batch, Nn);
    head_kernel<<<NG, D>>>(W1, b1, W2, b2, W3, b3, (float*)d_out);
}

// round 4
// speedup vs baseline: 1.7313x; 1.2591x over previous
#include <cuda_runtime.h>
#include <cuda_bf16.h>
#include <math.h>
#include <stdint.h>

#define D    256
#define R    8
#define NG   64
#define NMAX 50176          // 392*128
#define EPS  1e-5f
#define KTOT 2304           // (R+1)*D
#define NST  72             // KTOT / 32
#define BM   128
#define BN   128
#define EMAX 1048576

// smem: bf16 rows, stride 40 elems (80B) -> conflict-free ldmatrix
#define LDA   40
#define OAHI  0
#define OALO  10240
#define OBHI  20480
#define OBLO  30720
#define STG   40960
#define NSTAGE 3
#define SMEM_TOTAL (NSTAGE * STG)

// ---------------- static device scratch ----------------
__device__ __nv_bfloat16 g_Ahi[(size_t)NMAX * KTOT];  // [n][k] full A incl. x part
__device__ __nv_bfloat16 g_Alo[(size_t)NMAX * KTOT];
__device__ __nv_bfloat16 g_Bhi[(size_t)D * KTOT];     // [j][k]
__device__ __nv_bfloat16 g_Blo[(size_t)D * KTOT];
__device__ float  g_X0[(size_t)NMAX * D];
__device__ float  g_X1[(size_t)NMAX * D];
__device__ int    g_cnt[NMAX * R];
__device__ int    g_off[NMAX * R];
__device__ int    g_pos[NMAX * R];
__device__ int    g_bsum[2048];
__device__ int    g_esrc[EMAX];
__device__ double g_stats[2];
__device__ float  g_pool[NG * D];
__device__ int    g_gcnt[NG];

// ---------------- helpers ----------------
__device__ __forceinline__ uint32_t smem_u32(const void* p) {
    return (uint32_t)__cvta_generic_to_shared((void*)p);
}
__device__ __forceinline__ void red_add_v4(float* addr, float4 v) {
    asm volatile("red.global.add.v4.f32 [%0], {%1,%2,%3,%4};"
                 :: "l"(addr), "f"(v.x), "f"(v.y), "f"(v.z), "f"(v.w) : "memory");
}
__device__ __forceinline__ void ldsm4(uint32_t (&r)[4], uint32_t addr) {
    asm volatile("ldmatrix.sync.aligned.m8n8.x4.shared.b16 {%0,%1,%2,%3}, [%4];"
                 : "=r"(r[0]), "=r"(r[1]), "=r"(r[2]), "=r"(r[3]) : "r"(addr));
}
__device__ __forceinline__ void mma16816(float (&d)[4], const uint32_t (&a)[4],
                                         uint32_t b0, uint32_t b1) {
    asm volatile(
        "mma.sync.aligned.m16n8k16.row.col.f32.bf16.bf16.f32 "
        "{%0,%1,%2,%3}, {%4,%5,%6,%7}, {%8,%9}, {%0,%1,%2,%3};"
        : "+f"(d[0]), "+f"(d[1]), "+f"(d[2]), "+f"(d[3])
        : "r"(a[0]), "r"(a[1]), "r"(a[2]), "r"(a[3]), "r"(b0), "r"(b1));
}
__device__ __forceinline__ void cp16(uint32_t dst, const void* src) {
    asm volatile("cp.async.cg.shared.global [%0], [%1], 16;" :: "r"(dst), "l"(src));
}
__device__ __forceinline__ void cp_commit() {
    asm volatile("cp.async.commit_group;" ::: "memory");
}
template <int N> __device__ __forceinline__ void cp_wait() {
    asm volatile("cp.async.wait_group %0;" :: "n"(N) : "memory");
}
__device__ __forceinline__ void split8(const float* v, uint32_t* hw, uint32_t* lw) {
    #pragma unroll
    for (int p = 0; p < 4; p++) {
        __nv_bfloat16 h0 = __float2bfloat16(v[2 * p]);
        __nv_bfloat16 h1 = __float2bfloat16(v[2 * p + 1]);
        float l0 = v[2 * p]     - __bfloat162float(h0);
        float l1 = v[2 * p + 1] - __bfloat162float(h1);
        __nv_bfloat162 hh = __halves2bfloat162(h0, h1);
        __nv_bfloat162 ll = __floats2bfloat162_rn(l0, l1);
        hw[p] = *reinterpret_cast<uint32_t*>(&hh);
        lw[p] = *reinterpret_cast<uint32_t*>(&ll);
    }
}

// ---------------- CSR build (once) ----------------
__global__ void count_kernel(const int* __restrict__ dst, const int* __restrict__ et, int E) {
    int i = blockIdx.x * blockDim.x + threadIdx.x;
    if (i < E) atomicAdd(&g_cnt[dst[i] * R + et[i]], 1);
}

__global__ void scan_local(int L) {
    __shared__ int sh[256];
    int tid = threadIdx.x;
    int i = blockIdx.x * 256 + tid;
    int v = (i < L) ? g_cnt[i] : 0;
    sh[tid] = v; __syncthreads();
    #pragma unroll
    for (int o = 1; o < 256; o <<= 1) {
        int t = (tid >= o) ? sh[tid - o] : 0;
        __syncthreads();
        sh[tid] += t;
        __syncthreads();
    }
    if (i < L) g_off[i] = sh[tid] - v;
    if (tid == 255) g_bsum[blockIdx.x] = sh[255];
}

__global__ void scan_bsum(int nb) {
    __shared__ int sh[256];
    int tid = threadIdx.x;
    const int C = (nb + 255) / 256;   // <= 8 for nb <= 2048
    int loc[8];
    int s = 0;
    for (int i = 0; i < C; i++) {
        int idx = tid * C + i;
        int v = (idx < nb) ? g_bsum[idx] : 0;
        loc[i] = v; s += v;
    }
    sh[tid] = s; __syncthreads();
    #pragma unroll
    for (int o = 1; o < 256; o <<= 1) {
        int t = (tid >= o) ? sh[tid - o] : 0;
        __syncthreads();
        sh[tid] += t;
        __syncthreads();
    }
    int excl = sh[tid] - s;
    for (int i = 0; i < C; i++) {
        int idx = tid * C + i;
        if (idx < nb) { g_bsum[idx] = excl; excl += loc[i]; }
    }
}

__global__ void scan_add(int L) {
    int i = blockIdx.x * blockDim.x + threadIdx.x;
    if (i < L) {
        int v = g_off[i] + g_bsum[i >> 8];
        g_off[i] = v;
        g_pos[i] = v;
    }
}

__global__ void place_kernel(const int* __restrict__ src, const int* __restrict__ dst,
                             const int* __restrict__ et, int E) {
    int e = blockIdx.x * blockDim.x + threadIdx.x;
    if (e < E) {
        int seg = dst[e] * R + et[e];
        int p = atomicAdd(&g_pos[seg], 1);
        g_esrc[p] = src[e];
    }
}

// ---------------- weight prep: transpose + bf16 hi/lo split ----------------
__global__ void prep_B(const float* __restrict__ Wrel, const float* __restrict__ Wroot) {
    __shared__ float s[32][33];
    int k0 = blockIdx.x * 32, j0 = blockIdx.y * 32;
    for (int i = threadIdx.y; i < 32; i += 8) {
        int k = k0 + i;
        const float* row = (k < R * D) ? (Wrel + (size_t)k * D)
                                       : (Wroot + (size_t)(k - R * D) * D);
        s[i][threadIdx.x] = row[j0 + threadIdx.x];
    }
    __syncthreads();
    for (int i = threadIdx.y; i < 32; i += 8) {
        int j = j0 + i;
        float v = s[threadIdx.x][i];
        __nv_bfloat16 hi = __float2bfloat16(v);
        float lo = v - __bfloat162float(hi);
        g_Bhi[(size_t)j * KTOT + k0 + threadIdx.x] = hi;
        g_Blo[(size_t)j * KTOT + k0 + threadIdx.x] = __float2bfloat16(lo);
    }
}

// ---------------- aggregate: one warp per (node, rel) segment -> bf16 hi/lo A ----------------
__global__ __launch_bounds__(256) void aggregate(const float* __restrict__ x, int Nn) {
    int wid = threadIdx.x >> 5, lane = threadIdx.x & 31;
    int seg = blockIdx.x * 8 + wid;            // 0 .. NMAX*R-1
    int n = seg >> 3, r = seg & 7;
    int cnt = g_cnt[seg];
    int off = g_off[seg];
    float a[8] = {0, 0, 0, 0, 0, 0, 0, 0};
    for (int i = 0; i < cnt; i++) {
        int s = g_esrc[off + i];
        const float4* xp = (const float4*)(x + (size_t)s * D + lane * 8);
        float4 p0 = __ldg(xp), p1 = __ldg(xp + 1);
        a[0] += p0.x; a[1] += p0.y; a[2] += p0.z; a[3] += p0.w;
        a[4] += p1.x; a[5] += p1.y; a[6] += p1.z; a[7] += p1.w;
    }
    float sc = 1.0f / (float)max(cnt, 1);
    #pragma unroll
    for (int q = 0; q < 8; q++) a[q] *= sc;
    uint32_t hw[4], lw[4];
    split8(a, hw, lw);
    size_t o = (size_t)n * KTOT + r * D + lane * 8;
    *(uint4*)(g_Ahi + o) = make_uint4(hw[0], hw[1], hw[2], hw[3]);
    *(uint4*)(g_Alo + o) = make_uint4(lw[0], lw[1], lw[2], lw[3]);
}

// ---------------- x -> bf16 hi/lo into A columns [2048, 2304) ----------------
__global__ void xconvert(const float* __restrict__ x, int Nn) {
    int idx = blockIdx.x * blockDim.x + threadIdx.x;   // NMAX*32 threads
    int n = idx >> 5, c8 = (idx & 31) * 8;
    if (n >= NMAX) return;
    float v[8] = {0, 0, 0, 0, 0, 0, 0, 0};
    if (n < Nn) {
        float4 p0 = *(const float4*)(x + (size_t)n * D + c8);
        float4 p1 = *(const float4*)(x + (size_t)n * D + c8 + 4);
        v[0] = p0.x; v[1] = p0.y; v[2] = p0.z; v[3] = p0.w;
        v[4] = p1.x; v[5] = p1.y; v[6] = p1.z; v[7] = p1.w;
    }
    uint32_t hw[4], lw[4];
    split8(v, hw, lw);
    size_t o = (size_t)n * KTOT + R * D + c8;
    *(uint4*)(g_Ahi + o) = make_uint4(hw[0], hw[1], hw[2], hw[3]);
    *(uint4*)(g_Alo + o) = make_uint4(lw[0], lw[1], lw[2], lw[3]);
}

// ---------------- pure-bf16 HMMA GEMM, 3-stage cp.async ----------------
__global__ __launch_bounds__(256) void rgcn_hmma(
    const float* __restrict__ Xcur,
    const float* __restrict__ bconv,
    float* __restrict__ Xnext, int Nn)
{
    extern __shared__ char sm[];
    uint32_t sbase = smem_u32(sm);
    int tid = threadIdx.x, lane = tid & 31, wid = tid >> 5;
    int wm = wid & 1, wn = wid >> 1;
    int col0 = blockIdx.x * BN, row0 = blockIdx.y * BM;

    float acc[4][4][4];
    #pragma unroll
    for (int i = 0; i < 4; i++)
        #pragma unroll
        for (int j = 0; j < 4; j++)
            #pragma unroll
            for (int q = 0; q < 4; q++) acc[i][j][q] = 0.f;

    int crow = tid >> 1, chalf = tid & 1;
    const __nv_bfloat16* gAh = g_Ahi + (size_t)(row0 + crow) * KTOT + chalf * 16;
    const __nv_bfloat16* gAl = g_Alo + (size_t)(row0 + crow) * KTOT + chalf * 16;
    const __nv_bfloat16* gBh = g_Bhi + (size_t)(col0 + crow) * KTOT + chalf * 16;
    const __nv_bfloat16* gBl = g_Blo + (size_t)(col0 + crow) * KTOT + chalf * 16;
    uint32_t dbase = (uint32_t)(crow * (LDA * 2) + chalf * 32);

    auto issue = [&](int kt, int b) {
        uint32_t st = sbase + b * STG + dbase;
        int ko = kt * 32;
        cp16(st + OAHI, gAh + ko); cp16(st + OAHI + 16, gAh + ko + 8);
        cp16(st + OALO, gAl + ko); cp16(st + OALO + 16, gAl + ko + 8);
        cp16(st + OBHI, gBh + ko); cp16(st + OBHI + 16, gBh + ko + 8);
        cp16(st + OBLO, gBl + ko); cp16(st + OBLO + 16, gBl + ko + 8);
    };

    issue(0, 0); cp_commit();
    issue(1, 1); cp_commit();
    issue(2, 2); cp_commit();

    uint32_t a_row_off = (uint32_t)((wm * 64 + (lane & 15)) * (LDA * 2));
    uint32_t b_row_off = (uint32_t)((wn * 32 + (lane & 15)) * (LDA * 2));
    uint32_t k_half = (uint32_t)((lane >> 4) * 16);

    #pragma unroll 1
    for (int kt = 0; kt < NST; kt++) {
        int b = kt % NSTAGE;
        cp_wait<NSTAGE - 1>();
        __syncthreads();

        uint32_t sb = sbase + b * STG;
        #pragma unroll
        for (int ks = 0; ks < 2; ks++) {
            uint32_t koff = ks * 32 + k_half;
            uint32_t ah[4][4], al[4][4];
            #pragma unroll
            for (int mi = 0; mi < 4; mi++) {
                uint32_t ad = sb + a_row_off + mi * 16 * (LDA * 2) + koff;
                ldsm4(ah[mi], ad + OAHI);
                ldsm4(al[mi], ad + OALO);
            }
            uint32_t bhf[2][4], blf[2][4];
            #pragma unroll
            for (int nj2 = 0; nj2 < 2; nj2++) {
                uint32_t bd = sb + b_row_off + nj2 * 16 * (LDA * 2) + koff;
                ldsm4(bhf[nj2], bd + OBHI);
                ldsm4(blf[nj2], bd + OBLO);
            }
            #pragma unroll
            for (int mi = 0; mi < 4; mi++) {
                #pragma unroll
                for (int nj2 = 0; nj2 < 2; nj2++) {
                    mma16816(acc[mi][nj2 * 2],     ah[mi], bhf[nj2][0], bhf[nj2][2]);
                    mma16816(acc[mi][nj2 * 2],     ah[mi], blf[nj2][0], blf[nj2][2]);
                    mma16816(acc[mi][nj2 * 2],     al[mi], bhf[nj2][0], bhf[nj2][2]);
                    mma16816(acc[mi][nj2 * 2 + 1], ah[mi], bhf[nj2][1], bhf[nj2][3]);
                    mma16816(acc[mi][nj2 * 2 + 1], ah[mi], blf[nj2][1], blf[nj2][3]);
                    mma16816(acc[mi][nj2 * 2 + 1], al[mi], bhf[nj2][1], bhf[nj2][3]);
                }
            }
        }
        __syncthreads();
        if (kt + NSTAGE < NST) issue(kt + NSTAGE, b);
        cp_commit();
    }

    // ---- epilogue: bias + residual + relu ----
    int gr = lane >> 2, gc = lane & 3;
    #pragma unroll
    for (int mi = 0; mi < 4; mi++) {
        #pragma unroll
        for (int half = 0; half < 2; half++) {
            int n = row0 + wm * 64 + mi * 16 + gr + half * 8;
            if (n >= Nn) continue;
            #pragma unroll
            for (int nj = 0; nj < 4; nj++) {
                int col = col0 + wn * 32 + nj * 8 + gc * 2;
                float2 xv = *(const float2*)(Xcur + (size_t)n * D + col);
                float2 bv = *(const float2*)(bconv + col);
                float2 o;
                o.x = fmaxf(acc[mi][nj][half * 2 + 0] + bv.x + xv.x, 0.f);
                o.y = fmaxf(acc[mi][nj][half * 2 + 1] + bv.y + xv.y, 0.f);
                *(float2*)(Xnext + (size_t)n * D + col) = o;
            }
        }
    }
}

// ---------------- whole-tensor layernorm ----------------
__global__ void ln_reduce(const float* __restrict__ X, int M) {
    double s = 0.0, q = 0.0;
    for (int i = blockIdx.x * blockDim.x + threadIdx.x; i < M; i += gridDim.x * blockDim.x) {
        float v = X[i];
        s += (double)v;
        q += (double)v * (double)v;
    }
    #pragma unroll
    for (int o = 16; o > 0; o >>= 1) {
        s += __shfl_down_sync(0xffffffffu, s, o);
        q += __shfl_down_sync(0xffffffffu, q, o);
    }
    __shared__ double sh[8], qh[8];
    int lane = threadIdx.x & 31, w = threadIdx.x >> 5;
    if (lane == 0) { sh[w] = s; qh[w] = q; }
    __syncthreads();
    if (w == 0) {
        s = (lane < (blockDim.x >> 5)) ? sh[lane] : 0.0;
        q = (lane < (blockDim.x >> 5)) ? qh[lane] : 0.0;
        #pragma unroll
        for (int o = 4; o > 0; o >>= 1) {
            s += __shfl_down_sync(0xffffffffu, s, o);
            q += __shfl_down_sync(0xffffffffu, q, o);
        }
        if (lane == 0) {
            atomicAdd(&g_stats[0], s);
            atomicAdd(&g_stats[1], q);
        }
    }
}

__global__ void ln_apply(float* __restrict__ X,
                         const float* __restrict__ w,
                         const float* __restrict__ b, int M) {
    int i = blockIdx.x * blockDim.x + threadIdx.x;
    if (i >= M) return;
    double invM = 1.0 / (double)M;
    float mu = (float)(g_stats[0] * invM);
    float var = (float)(g_stats[1] * invM - (g_stats[0] * invM) * (g_stats[0] * invM));
    float sd = sqrtf(fmaxf(var, 0.f));
    float rs = 1.0f / (sd + EPS);
    int j = i & (D - 1);
    X[i] = w[j] * ((X[i] - mu) * rs) + b[j];
}

// ---------------- global mean pool + head ----------------
__global__ void pool_cnt(const int* __restrict__ batch, int Nn) {
    int i = blockIdx.x * blockDim.x + threadIdx.x;
    if (i < Nn) atomicAdd(&g_gcnt[batch[i]], 1);
}
__global__ void pool_sum(const float* __restrict__ X, const int* __restrict__ batch, int Nn) {
    int idx = blockIdx.x * blockDim.x + threadIdx.x;
    if (idx >= Nn * (D / 4)) return;
    int n = idx >> 6, c = idx & 63;
    float4 v = ((const float4*)X)[(size_t)n * (D / 4) + c];
    red_add_v4(g_pool + batch[n] * D + c * 4, v);
}
__global__ void head_kernel(const float* __restrict__ W1, const float* __restrict__ b1,
                            const float* __restrict__ W2, const float* __restrict__ b2,
                            const float* __restrict__ W3, const float* __restrict__ b3,
                            float* __restrict__ out) {
    __shared__ float g[D], h1[D], h2[D];
    int bg = blockIdx.x, j = threadIdx.x;
    float c = fmaxf((float)g_gcnt[bg], 1.f);
    g[j] = g_pool[bg * D + j] / c;
    __syncthreads();
    float acc = b1[j];
    for (int k = 0; k < D; k++) acc = fmaf(g[k], W1[k * D + j], acc);
    h1[j] = fmaxf(acc, 0.f);
    __syncthreads();
    acc = b2[j];
    for (int k = 0; k < D; k++) acc = fmaf(h1[k], W2[k * D + j], acc);
    h2[j] = fmaxf(acc, 0.f);
    __syncthreads();
    if (j < 4) {
        acc = b3[j];
        for (int k = 0; k < D; k++) acc = fmaf(h2[k], W3[k * 4 + j], acc);
        out[bg * 4 + j] = acc;
    }
}

// ---------------- launch ----------------
extern "C" void kernel_launch(void* const* d_in, const int* in_sizes, int n_in,
                              void* d_out, int out_size) {
    const float* x      = (const float*)d_in[0];
    const int*   ei     = (const int*)d_in[1];
    const int*   et     = (const int*)d_in[2];
    const int*   batch  = (const int*)d_in[3];
    const float* W_rel  = (const float*)d_in[4];
    const float* W_root = (const float*)d_in[5];
    const float* b_conv = (const float*)d_in[6];
    const float* ln_w   = (const float*)d_in[7];
    const float* ln_b   = (const float*)d_in[8];
    const float* W1 = (const float*)d_in[9];
    const float* b1 = (const float*)d_in[10];
    const float* W2 = (const float*)d_in[11];
    const float* b2 = (const float*)d_in[12];
    const float* W3 = (const float*)d_in[13];
    const float* b3 = (const float*)d_in[14];

    int E  = in_sizes[1] / 2;
    int Nn = in_sizes[0] / D;
    const int* src = ei;
    const int* dst = ei + E;
    int L = Nn * R;
    int nb = (L + 255) / 256;

    cudaFuncSetAttribute(rgcn_hmma, cudaFuncAttributeMaxDynamicSharedMemorySize, SMEM_TOTAL);

    void *pCnt, *pStats, *pPool, *pGcnt;
    cudaGetSymbolAddress(&pCnt, g_cnt);
    cudaGetSymbolAddress(&pStats, g_stats);
    cudaGetSymbolAddress(&pPool, g_pool);
    cudaGetSymbolAddress(&pGcnt, g_gcnt);

    // ---- CSR build (once per call) ----
    cudaMemsetAsync(pCnt, 0, (size_t)NMAX * R * sizeof(int));
    count_kernel<<<(E + 255) / 256, 256>>>(dst, et, E);
    scan_local<<<nb, 256>>>(L);
    scan_bsum<<<1, 256>>>(nb);
    scan_add<<<nb, 256>>>(L);
    place_kernel<<<(E + 255) / 256, 256>>>(src, dst, et, E);

    const float* cur = x;
    float* bufs[2];
    cudaGetSymbolAddress((void**)&bufs[0], g_X0);
    cudaGetSymbolAddress((void**)&bufs[1], g_X1);

    for (int l = 0; l < 3; l++) {
        prep_B<<<dim3(KTOT / 32, D / 32), dim3(32, 8)>>>(
            W_rel + (size_t)l * R * D * D, W_root + (size_t)l * D * D);
        aggregate<<<NMAX, 256>>>(cur, Nn);
        xconvert<<<NMAX * 32 / 256, 256>>>(cur, Nn);
        float* nxt = bufs[l & 1];
        rgcn_hmma<<<dim3(D / BN, NMAX / BM), 256, SMEM_TOTAL>>>(
            cur, b_conv + l * D, nxt, Nn);
        if (l < 2) {
            cudaMemsetAsync(pStats, 0, 2 * sizeof(double));
            ln_reduce<<<1024, 256>>>(nxt, Nn * D);
            ln_apply<<<(Nn * D + 255) / 256, 256>>>(nxt, ln_w + l * D, ln_b + l * D, Nn * D);
        }
        cur = nxt;
    }

    cudaMemsetAsync(pPool, 0, NG * D * sizeof(float));
    cudaMemsetAsync(pGcnt, 0, NG * sizeof(int));
    pool_cnt<<<(Nn + 255) / 256, 256>>>(batch, Nn);
    pool_sum<<<(Nn * (D / 4) + 255) / 256, 256>>>(cur, batch, Nn);
    head_kernel<<<NG, D>>>(W1, b1, W2, b2, W3, b3, (float*)d_out);
}

// round 5
// speedup vs baseline: 1.7469x; 1.0090x over previous
#include <cuda_runtime.h>
#include <cuda_bf16.h>
#include <math.h>
#include <stdint.h>

#define D    256
#define R    8
#define NG   64
#define NMAX 50176          // 392*128
#define EPS  1e-5f
#define KTOT 2304           // (R+1)*D
#define NST  72             // KTOT / 32
#define BM   128
#define BN   256
#define EMAX 1048576

// smem: bf16 rows, stride 40 elems (80B) -> conflict-free ldmatrix
#define LDA   40
#define OAHI  0
#define OALO  10240
#define OBHI  20480
#define OBLO  40960
#define STG   61440
#define NSTAGE 3
#define SMEM_TOTAL (NSTAGE * STG)

// ---------------- static device scratch ----------------
__device__ __nv_bfloat16 g_Ahi[(size_t)NMAX * KTOT];
__device__ __nv_bfloat16 g_Alo[(size_t)NMAX * KTOT];
__device__ __nv_bfloat16 g_Bhi[(size_t)D * KTOT];
__device__ __nv_bfloat16 g_Blo[(size_t)D * KTOT];
__device__ float  g_X0[(size_t)NMAX * D];
__device__ float  g_X1[(size_t)NMAX * D];
__device__ int    g_cnt[NMAX * R];
__device__ int    g_off[NMAX * R];
__device__ int    g_pos[NMAX * R];
__device__ int    g_bsum[2048];
__device__ int    g_esrc[EMAX];
__device__ double g_lnstats[3][2];
__device__ float  g_pool[NG * D];
__device__ int    g_gcnt[NG];

// ---------------- helpers ----------------
__device__ __forceinline__ uint32_t smem_u32(const void* p) {
    return (uint32_t)__cvta_generic_to_shared((void*)p);
}
__device__ __forceinline__ void red_add_v4(float* addr, float4 v) {
    asm volatile("red.global.add.v4.f32 [%0], {%1,%2,%3,%4};"
                 :: "l"(addr), "f"(v.x), "f"(v.y), "f"(v.z), "f"(v.w) : "memory");
}
__device__ __forceinline__ void ldsm4(uint32_t (&r)[4], uint32_t addr) {
    asm volatile("ldmatrix.sync.aligned.m8n8.x4.shared.b16 {%0,%1,%2,%3}, [%4];"
                 : "=r"(r[0]), "=r"(r[1]), "=r"(r[2]), "=r"(r[3]) : "r"(addr));
}
__device__ __forceinline__ void mma16816(float (&d)[4], const uint32_t (&a)[4],
                                         uint32_t b0, uint32_t b1) {
    asm volatile(
        "mma.sync.aligned.m16n8k16.row.col.f32.bf16.bf16.f32 "
        "{%0,%1,%2,%3}, {%4,%5,%6,%7}, {%8,%9}, {%0,%1,%2,%3};"
        : "+f"(d[0]), "+f"(d[1]), "+f"(d[2]), "+f"(d[3])
        : "r"(a[0]), "r"(a[1]), "r"(a[2]), "r"(a[3]), "r"(b0), "r"(b1));
}
__device__ __forceinline__ void cp16(uint32_t dst, const void* src) {
    asm volatile("cp.async.cg.shared.global [%0], [%1], 16;" :: "r"(dst), "l"(src));
}
__device__ __forceinline__ void cp_commit() {
    asm volatile("cp.async.commit_group;" ::: "memory");
}
template <int N> __device__ __forceinline__ void cp_wait() {
    asm volatile("cp.async.wait_group %0;" :: "n"(N) : "memory");
}
__device__ __forceinline__ void split8(const float* v, uint32_t* hw, uint32_t* lw) {
    #pragma unroll
    for (int p = 0; p < 4; p++) {
        __nv_bfloat16 h0 = __float2bfloat16(v[2 * p]);
        __nv_bfloat16 h1 = __float2bfloat16(v[2 * p + 1]);
        float l0 = v[2 * p]     - __bfloat162float(h0);
        float l1 = v[2 * p + 1] - __bfloat162float(h1);
        __nv_bfloat162 hh = __halves2bfloat162(h0, h1);
        __nv_bfloat162 ll = __floats2bfloat162_rn(l0, l1);
        hw[p] = *reinterpret_cast<uint32_t*>(&hh);
        lw[p] = *reinterpret_cast<uint32_t*>(&ll);
    }
}
__device__ __forceinline__ void ln_params(const double* st, int M, float& mu, float& rs) {
    double m = st[0] / (double)M;
    double var = st[1] / (double)M - m * m;
    mu = (float)m;
    rs = 1.0f / ((float)sqrt(fmax(var, 0.0)) + EPS);
}

// ---------------- CSR build (once) ----------------
__global__ void count_kernel(const int* __restrict__ dst, const int* __restrict__ et, int E) {
    int i = blockIdx.x * blockDim.x + threadIdx.x;
    if (i < E) atomicAdd(&g_cnt[dst[i] * R + et[i]], 1);
}

__global__ void scan_local(int L) {
    __shared__ int sh[256];
    int tid = threadIdx.x;
    int i = blockIdx.x * 256 + tid;
    int v = (i < L) ? g_cnt[i] : 0;
    sh[tid] = v; __syncthreads();
    #pragma unroll
    for (int o = 1; o < 256; o <<= 1) {
        int t = (tid >= o) ? sh[tid - o] : 0;
        __syncthreads();
        sh[tid] += t;
        __syncthreads();
    }
    if (i < L) g_off[i] = sh[tid] - v;
    if (tid == 255) g_bsum[blockIdx.x] = sh[255];
}

__global__ void scan_bsum(int nb) {
    __shared__ int sh[256];
    int tid = threadIdx.x;
    const int C = (nb + 255) / 256;
    int loc[8];
    int s = 0;
    for (int i = 0; i < C; i++) {
        int idx = tid * C + i;
        int v = (idx < nb) ? g_bsum[idx] : 0;
        loc[i] = v; s += v;
    }
    sh[tid] = s; __syncthreads();
    #pragma unroll
    for (int o = 1; o < 256; o <<= 1) {
        int t = (tid >= o) ? sh[tid - o] : 0;
        __syncthreads();
        sh[tid] += t;
        __syncthreads();
    }
    int excl = sh[tid] - s;
    for (int i = 0; i < C; i++) {
        int idx = tid * C + i;
        if (idx < nb) { g_bsum[idx] = excl; excl += loc[i]; }
    }
}

__global__ void scan_add(int L) {
    int i = blockIdx.x * blockDim.x + threadIdx.x;
    if (i < L) {
        int v = g_off[i] + g_bsum[i >> 8];
        g_off[i] = v;
        g_pos[i] = v;
    }
}

__global__ void place_kernel(const int* __restrict__ src, const int* __restrict__ dst,
                             const int* __restrict__ et, int E) {
    int e = blockIdx.x * blockDim.x + threadIdx.x;
    if (e < E) {
        int seg = dst[e] * R + et[e];
        int p = atomicAdd(&g_pos[seg], 1);
        g_esrc[p] = src[e];
    }
}

// ---------------- weight prep: transpose + bf16 hi/lo split ----------------
__global__ void prep_B(const float* __restrict__ Wrel, const float* __restrict__ Wroot) {
    __shared__ float s[32][33];
    int k0 = blockIdx.x * 32, j0 = blockIdx.y * 32;
    for (int i = threadIdx.y; i < 32; i += 8) {
        int k = k0 + i;
        const float* row = (k < R * D) ? (Wrel + (size_t)k * D)
                                       : (Wroot + (size_t)(k - R * D) * D);
        s[i][threadIdx.x] = row[j0 + threadIdx.x];
    }
    __syncthreads();
    for (int i = threadIdx.y; i < 32; i += 8) {
        int j = j0 + i;
        float v = s[threadIdx.x][i];
        __nv_bfloat16 hi = __float2bfloat16(v);
        float lo = v - __bfloat162float(hi);
        g_Bhi[(size_t)j * KTOT + k0 + threadIdx.x] = hi;
        g_Blo[(size_t)j * KTOT + k0 + threadIdx.x] = __float2bfloat16(lo);
    }
}

// ---------------- aggregate: warp per (node, rel) segment; lazy-LN affine ----------------
__global__ __launch_bounds__(256) void aggregate(
    const float* __restrict__ x,
    const float* __restrict__ lnw, const float* __restrict__ lnb,
    const double* __restrict__ stats, int M, int Nn)
{
    int wid = threadIdx.x >> 5, lane = threadIdx.x & 31;
    int seg = blockIdx.x * 8 + wid;
    int n = seg >> 3, r = seg & 7;
    int cnt = g_cnt[seg];
    int off = g_off[seg];
    float a[8] = {0, 0, 0, 0, 0, 0, 0, 0};
    for (int i = 0; i < cnt; i++) {
        int s = g_esrc[off + i];
        const float4* xp = (const float4*)(x + (size_t)s * D + lane * 8);
        float4 p0 = __ldg(xp), p1 = __ldg(xp + 1);
        a[0] += p0.x; a[1] += p0.y; a[2] += p0.z; a[3] += p0.w;
        a[4] += p1.x; a[5] += p1.y; a[6] += p1.z; a[7] += p1.w;
    }
    float sc = 1.0f / (float)max(cnt, 1);
    #pragma unroll
    for (int q = 0; q < 8; q++) a[q] *= sc;
    if (stats != nullptr && cnt > 0) {
        float mu, rs;
        ln_params(stats, M, mu, rs);
        #pragma unroll
        for (int q = 0; q < 8; q++) {
            int c = lane * 8 + q;
            a[q] = lnw[c] * ((a[q] - mu) * rs) + lnb[c];
        }
    }
    uint32_t hw[4], lw[4];
    split8(a, hw, lw);
    size_t o = (size_t)n * KTOT + r * D + lane * 8;
    *(uint4*)(g_Ahi + o) = make_uint4(hw[0], hw[1], hw[2], hw[3]);
    *(uint4*)(g_Alo + o) = make_uint4(lw[0], lw[1], lw[2], lw[3]);
}

// ---------------- x -> bf16 hi/lo into A cols [2048,2304); lazy-LN affine ----------------
__global__ void xconvert(const float* __restrict__ x,
                         const float* __restrict__ lnw, const float* __restrict__ lnb,
                         const double* __restrict__ stats, int M, int Nn)
{
    int idx = blockIdx.x * blockDim.x + threadIdx.x;
    int n = idx >> 5, c8 = (idx & 31) * 8;
    if (n >= NMAX) return;
    float v[8] = {0, 0, 0, 0, 0, 0, 0, 0};
    if (n < Nn) {
        float4 p0 = *(const float4*)(x + (size_t)n * D + c8);
        float4 p1 = *(const float4*)(x + (size_t)n * D + c8 + 4);
        v[0] = p0.x; v[1] = p0.y; v[2] = p0.z; v[3] = p0.w;
        v[4] = p1.x; v[5] = p1.y; v[6] = p1.z; v[7] = p1.w;
        if (stats != nullptr) {
            float mu, rs;
            ln_params(stats, M, mu, rs);
            #pragma unroll
            for (int q = 0; q < 8; q++)
                v[q] = lnw[c8 + q] * ((v[q] - mu) * rs) + lnb[c8 + q];
        }
    }
    uint32_t hw[4], lw[4];
    split8(v, hw, lw);
    size_t o = (size_t)n * KTOT + R * D + c8;
    *(uint4*)(g_Ahi + o) = make_uint4(hw[0], hw[1], hw[2], hw[3]);
    *(uint4*)(g_Alo + o) = make_uint4(lw[0], lw[1], lw[2], lw[3]);
}

// ---------------- bf16 HMMA GEMM, BN=256, 512 threads, 3-stage cp.async ----------------
// out = relu(A@Wcat + b + affine(x)); accumulates sum/sumsq of outputs if statsOut != 0
__global__ __launch_bounds__(512) void rgcn_hmma(
    const float* __restrict__ Xcur,
    const float* __restrict__ bconv,
    float* __restrict__ Xnext, int Nn,
    const float* __restrict__ pw, const float* __restrict__ pb,
    const double* __restrict__ statsPrev,
    double* __restrict__ statsOut, int M)
{
    extern __shared__ char sm[];
    uint32_t sbase = smem_u32(sm);
    int tid = threadIdx.x, lane = tid & 31, wid = tid >> 5;
    int wm = wid & 3, wn = wid >> 2;            // rows wm*32, cols wn*64
    int row0 = blockIdx.x * BM;

    float acc[2][8][4];
    #pragma unroll
    for (int i = 0; i < 2; i++)
        #pragma unroll
        for (int j = 0; j < 8; j++)
            #pragma unroll
            for (int q = 0; q < 4; q++) acc[i][j][q] = 0.f;

    // loaders
    int arow = tid >> 2, aq = tid & 3;
    const __nv_bfloat16* gAh = g_Ahi + (size_t)(row0 + arow) * KTOT + aq * 8;
    const __nv_bfloat16* gAl = g_Alo + (size_t)(row0 + arow) * KTOT + aq * 8;
    uint32_t adst = (uint32_t)(arow * (LDA * 2) + aq * 16);
    int brow = tid >> 1, bh2 = tid & 1;
    const __nv_bfloat16* gBh = g_Bhi + (size_t)brow * KTOT + bh2 * 16;
    const __nv_bfloat16* gBl = g_Blo + (size_t)brow * KTOT + bh2 * 16;
    uint32_t bdst = (uint32_t)(brow * (LDA * 2) + bh2 * 32);

    auto issue = [&](int kt, int b) {
        uint32_t st = sbase + b * STG;
        int ko = kt * 32;
        cp16(st + OAHI + adst, gAh + ko);
        cp16(st + OALO + adst, gAl + ko);
        cp16(st + OBHI + bdst, gBh + ko);      cp16(st + OBHI + bdst + 16, gBh + ko + 8);
        cp16(st + OBLO + bdst, gBl + ko);      cp16(st + OBLO + bdst + 16, gBl + ko + 8);
    };

    issue(0, 0); cp_commit();
    issue(1, 1); cp_commit();
    issue(2, 2); cp_commit();

    uint32_t a_row_off = (uint32_t)((wm * 32 + (lane & 15)) * (LDA * 2));
    uint32_t b_row_off = (uint32_t)((wn * 64 + (lane & 15)) * (LDA * 2));
    uint32_t k_half = (uint32_t)((lane >> 4) * 16);

    #pragma unroll 1
    for (int kt = 0; kt < NST; kt++) {
        int b = kt % NSTAGE;
        cp_wait<NSTAGE - 1>();
        __syncthreads();

        uint32_t sb = sbase + b * STG;
        #pragma unroll
        for (int ks = 0; ks < 2; ks++) {
            uint32_t koff = ks * 32 + k_half;
            uint32_t ah[2][4], al[2][4];
            #pragma unroll
            for (int mi = 0; mi < 2; mi++) {
                uint32_t ad = sb + a_row_off + mi * 16 * (LDA * 2) + koff;
                ldsm4(ah[mi], ad + OAHI);
                ldsm4(al[mi], ad + OALO);
            }
            #pragma unroll
            for (int nj2 = 0; nj2 < 4; nj2++) {
                uint32_t bd = sb + b_row_off + nj2 * 16 * (LDA * 2) + koff;
                uint32_t bhf[4], blf[4];
                ldsm4(bhf, bd + OBHI);
                ldsm4(blf, bd + OBLO);
                #pragma unroll
                for (int mi = 0; mi < 2; mi++) {
                    mma16816(acc[mi][nj2 * 2],     ah[mi], bhf[0], bhf[2]);
                    mma16816(acc[mi][nj2 * 2],     ah[mi], blf[0], blf[2]);
                    mma16816(acc[mi][nj2 * 2],     al[mi], bhf[0], bhf[2]);
                    mma16816(acc[mi][nj2 * 2 + 1], ah[mi], bhf[1], bhf[3]);
                    mma16816(acc[mi][nj2 * 2 + 1], ah[mi], blf[1], blf[3]);
                    mma16816(acc[mi][nj2 * 2 + 1], al[mi], bhf[1], bhf[3]);
                }
            }
        }
        __syncthreads();
        if (kt + NSTAGE < NST) issue(kt + NSTAGE, b);
        cp_commit();
    }

    // ---- epilogue: bias + residual(affine) + relu + stats ----
    float mu = 0.f, rs = 0.f;
    bool ln = (statsPrev != nullptr);
    if (ln) ln_params(statsPrev, M, mu, rs);

    int gr = lane >> 2, gc = lane & 3;
    float ps = 0.f, pq = 0.f;
    #pragma unroll
    for (int mi = 0; mi < 2; mi++) {
        #pragma unroll
        for (int half = 0; half < 2; half++) {
            int n = row0 + wm * 32 + mi * 16 + gr + half * 8;
            if (n >= Nn) continue;
            #pragma unroll
            for (int nj = 0; nj < 8; nj++) {
                int col = wn * 64 + nj * 8 + gc * 2;
                float2 xv = *(const float2*)(Xcur + (size_t)n * D + col);
                float2 bv = *(const float2*)(bconv + col);
                if (ln) {
                    float2 wv = *(const float2*)(pw + col);
                    float2 bb = *(const float2*)(pb + col);
                    xv.x = wv.x * ((xv.x - mu) * rs) + bb.x;
                    xv.y = wv.y * ((xv.y - mu) * rs) + bb.y;
                }
                float2 o;
                o.x = fmaxf(acc[mi][nj][half * 2 + 0] + bv.x + xv.x, 0.f);
                o.y = fmaxf(acc[mi][nj][half * 2 + 1] + bv.y + xv.y, 0.f);
                *(float2*)(Xnext + (size_t)n * D + col) = o;
                ps += o.x + o.y;
                pq += o.x * o.x + o.y * o.y;
            }
        }
    }
    if (statsOut != nullptr) {
        #pragma unroll
        for (int o = 16; o > 0; o >>= 1) {
            ps += __shfl_down_sync(0xffffffffu, ps, o);
            pq += __shfl_down_sync(0xffffffffu, pq, o);
        }
        if (lane == 0) {
            atomicAdd(&statsOut[0], (double)ps);
            atomicAdd(&statsOut[1], (double)pq);
        }
    }
}

// ---------------- global mean pool + head ----------------
__global__ void pool_cnt(const int* __restrict__ batch, int Nn) {
    int i = blockIdx.x * blockDim.x + threadIdx.x;
    if (i < Nn) atomicAdd(&g_gcnt[batch[i]], 1);
}
__global__ void pool_sum(const float* __restrict__ X, const int* __restrict__ batch, int Nn) {
    int idx = blockIdx.x * blockDim.x + threadIdx.x;
    if (idx >= Nn * (D / 4)) return;
    int n = idx >> 6, c = idx & 63;
    float4 v = ((const float4*)X)[(size_t)n * (D / 4) + c];
    red_add_v4(g_pool + batch[n] * D + c * 4, v);
}
__global__ void head_kernel(const float* __restrict__ W1, const float* __restrict__ b1,
                            const float* __restrict__ W2, const float* __restrict__ b2,
                            const float* __restrict__ W3, const float* __restrict__ b3,
                            float* __restrict__ out) {
    __shared__ float g[D], h1[D], h2[D];
    int bg = blockIdx.x, j = threadIdx.x;
    float c = fmaxf((float)g_gcnt[bg], 1.f);
    g[j] = g_pool[bg * D + j] / c;
    __syncthreads();
    float acc = b1[j];
    for (int k = 0; k < D; k++) acc = fmaf(g[k], W1[k * D + j], acc);
    h1[j] = fmaxf(acc, 0.f);
    __syncthreads();
    acc = b2[j];
    for (int k = 0; k < D; k++) acc = fmaf(h1[k], W2[k * D + j], acc);
    h2[j] = fmaxf(acc, 0.f);
    __syncthreads();
    if (j < 4) {
        acc = b3[j];
        for (int k = 0; k < D; k++) acc = fmaf(h2[k], W3[k * 4 + j], acc);
        out[bg * 4 + j] = acc;
    }
}

// ---------------- launch ----------------
extern "C" void kernel_launch(void* const* d_in, const int* in_sizes, int n_in,
                              void* d_out, int out_size) {
    const float* x      = (const float*)d_in[0];
    const int*   ei     = (const int*)d_in[1];
    const int*   et     = (const int*)d_in[2];
    const int*   batch  = (const int*)d_in[3];
    const float* W_rel  = (const float*)d_in[4];
    const float* W_root = (const float*)d_in[5];
    const float* b_conv = (const float*)d_in[6];
    const float* ln_w   = (const float*)d_in[7];
    const float* ln_b   = (const float*)d_in[8];
    const float* W1 = (const float*)d_in[9];
    const float* b1 = (const float*)d_in[10];
    const float* W2 = (const float*)d_in[11];
    const float* b2 = (const float*)d_in[12];
    const float* W3 = (const float*)d_in[13];
    const float* b3 = (const float*)d_in[14];

    int E  = in_sizes[1] / 2;
    int Nn = in_sizes[0] / D;
    int M  = Nn * D;
    const int* src = ei;
    const int* dst = ei + E;
    int L = Nn * R;
    int nb = (L + 255) / 256;

    cudaFuncSetAttribute(rgcn_hmma, cudaFuncAttributeMaxDynamicSharedMemorySize, SMEM_TOTAL);

    void *pCnt, *pStats, *pPool, *pGcnt;
    cudaGetSymbolAddress(&pCnt, g_cnt);
    cudaGetSymbolAddress(&pStats, g_lnstats);
    cudaGetSymbolAddress(&pPool, g_pool);
    cudaGetSymbolAddress(&pGcnt, g_gcnt);
    double* pst = (double*)pStats;

    // ---- CSR build (once per call) ----
    cudaMemsetAsync(pCnt, 0, (size_t)NMAX * R * sizeof(int));
    cudaMemsetAsync(pStats, 0, 6 * sizeof(double));
    count_kernel<<<(E + 255) / 256, 256>>>(dst, et, E);
    scan_local<<<nb, 256>>>(L);
    scan_bsum<<<1, 256>>>(nb);
    scan_add<<<nb, 256>>>(L);
    place_kernel<<<(E + 255) / 256, 256>>>(src, dst, et, E);

    const float* cur = x;
    float* bufs[2];
    cudaGetSymbolAddress((void**)&bufs[0], g_X0);
    cudaGetSymbolAddress((void**)&bufs[1], g_X1);

    for (int l = 0; l < 3; l++) {
        prep_B<<<dim3(KTOT / 32, D / 32), dim3(32, 8)>>>(
            W_rel + (size_t)l * R * D * D, W_root + (size_t)l * D * D);
        const double* sp = (l > 0) ? (pst + (l - 1) * 2) : nullptr;
        const float* pw = (l > 0) ? (ln_w + (l - 1) * D) : nullptr;
        const float* pb = (l > 0) ? (ln_b + (l - 1) * D) : nullptr;
        aggregate<<<NMAX, 256>>>(cur, pw, pb, sp, M, Nn);
        xconvert<<<NMAX * 32 / 256, 256>>>(cur, pw, pb, sp, M, Nn);
        float* nxt = bufs[l & 1];
        double* so = (l < 2) ? (pst + l * 2) : nullptr;
        rgcn_hmma<<<NMAX / BM, 512, SMEM_TOTAL>>>(
            cur, b_conv + l * D, nxt, Nn, pw, pb, sp, so, M);
        cur = nxt;
    }

    cudaMemsetAsync(pPool, 0, NG * D * sizeof(float));
    cudaMemsetAsync(pGcnt, 0, NG * sizeof(int));
    pool_cnt<<<(Nn + 255) / 256, 256>>>(batch, Nn);
    pool_sum<<<(Nn * (D / 4) + 255) / 256, 256>>>(cur, batch, Nn);
    head_kernel<<<NG, D>>>(W1, b1, W2, b2, W3, b3, (float*)d_out);
}

// round 6
// speedup vs baseline: 1.8440x; 1.0556x over previous
#include <cuda_runtime.h>
#include <cuda_bf16.h>
#include <math.h>
#include <stdint.h>

#define D    256
#define R    8
#define NG   64
#define NMAX 50176          // 392*128
#define EPS  1e-5f
#define KTOT 2304           // (R+1)*D
#define NST  72             // KTOT / 32
#define BM   128
#define BN   256
#define EMAX 1048576

// smem: fp32(tf32) tiles, row stride 36 floats (conflict-free frag loads: bank = 4r+c)
#define LDAf  36
#define OA    0                         // A: 128 x 36 x 4 = 18432 B
#define OB    18432                     // B: 256 x 36 x 4 = 36864 B
#define STG   (18432 + 36864)           // 55296 B
#define NSTAGE 3
#define SMEM_TOTAL (NSTAGE * STG)       // 165888 B

// ---------------- static device scratch ----------------
__device__ float  g_A[(size_t)NMAX * KTOT];   // tf32-rounded fp32, [n][k]
__device__ float  g_B[(size_t)D * KTOT];      // tf32-rounded fp32, [j][k]
__device__ float  g_X0[(size_t)NMAX * D];
__device__ float  g_X1[(size_t)NMAX * D];
__device__ int    g_cnt[NMAX * R];
__device__ int    g_off[NMAX * R];
__device__ int    g_pos[NMAX * R];
__device__ int    g_cursor[1];
__device__ int    g_esrc[EMAX];
__device__ double g_lnstats[3][2];
__device__ float  g_pool[NG * D];
__device__ int    g_gcnt[NG];

// ---------------- helpers ----------------
__device__ __forceinline__ uint32_t smem_u32(const void* p) {
    return (uint32_t)__cvta_generic_to_shared((void*)p);
}
__device__ __forceinline__ void red_add_v4(float* addr, float4 v) {
    asm volatile("red.global.add.v4.f32 [%0], {%1,%2,%3,%4};"
                 :: "l"(addr), "f"(v.x), "f"(v.y), "f"(v.z), "f"(v.w) : "memory");
}
__device__ __forceinline__ void mma_tf32(float (&d)[4], const uint32_t (&a)[4],
                                         uint32_t b0, uint32_t b1) {
    asm volatile(
        "mma.sync.aligned.m16n8k8.row.col.f32.tf32.tf32.f32 "
        "{%0,%1,%2,%3}, {%4,%5,%6,%7}, {%8,%9}, {%0,%1,%2,%3};"
        : "+f"(d[0]), "+f"(d[1]), "+f"(d[2]), "+f"(d[3])
        : "r"(a[0]), "r"(a[1]), "r"(a[2]), "r"(a[3]), "r"(b0), "r"(b1));
}
__device__ __forceinline__ void cp16(uint32_t dst, const void* src) {
    asm volatile("cp.async.cg.shared.global [%0], [%1], 16;" :: "r"(dst), "l"(src));
}
__device__ __forceinline__ void cp_commit() {
    asm volatile("cp.async.commit_group;" ::: "memory");
}
template <int N> __device__ __forceinline__ void cp_wait() {
    asm volatile("cp.async.wait_group %0;" :: "n"(N) : "memory");
}
__device__ __forceinline__ uint32_t f2tf(float f) {
    uint32_t u;
    asm("cvt.rna.tf32.f32 %0, %1;" : "=r"(u) : "f"(f));
    return u;
}
__device__ __forceinline__ void ln_params(const double* st, int M, float& mu, float& rs) {
    double m = st[0] / (double)M;
    double var = st[1] / (double)M - m * m;
    mu = (float)m;
    rs = 1.0f / ((float)sqrt(fmax(var, 0.0)) + EPS);
}

// ---------------- CSR build ----------------
__global__ void count_kernel(const int* __restrict__ dst, const int* __restrict__ et, int E) {
    int i = blockIdx.x * blockDim.x + threadIdx.x;
    if (blockIdx.x == 0) {
        if (threadIdx.x < 6) ((double*)g_lnstats)[threadIdx.x] = 0.0;
        if (threadIdx.x == 6) g_cursor[0] = 0;
    }
    if (i < E) atomicAdd(&g_cnt[dst[i] * R + et[i]], 1);
}

__global__ void scan_atomic(int L) {
    __shared__ int sh[256];
    __shared__ int sbase;
    int tid = threadIdx.x;
    int i = blockIdx.x * 256 + tid;
    int v = (i < L) ? g_cnt[i] : 0;
    sh[tid] = v; __syncthreads();
    #pragma unroll
    for (int o = 1; o < 256; o <<= 1) {
        int t = (tid >= o) ? sh[tid - o] : 0;
        __syncthreads();
        sh[tid] += t;
        __syncthreads();
    }
    if (tid == 255) sbase = atomicAdd(&g_cursor[0], sh[255]);
    __syncthreads();
    if (i < L) {
        int o = sbase + sh[tid] - v;
        g_off[i] = o;
        g_pos[i] = o;
    }
}

__global__ void place_kernel(const int* __restrict__ src, const int* __restrict__ dst,
                             const int* __restrict__ et, int E) {
    int e = blockIdx.x * blockDim.x + threadIdx.x;
    if (e < E) {
        int seg = dst[e] * R + et[e];
        int p = atomicAdd(&g_pos[seg], 1);
        g_esrc[p] = src[e];
    }
}

// ---------------- weight prep: transpose + tf32 rounding ----------------
__global__ void prep_B(const float* __restrict__ Wrel, const float* __restrict__ Wroot) {
    __shared__ float s[32][33];
    int k0 = blockIdx.x * 32, j0 = blockIdx.y * 32;
    for (int i = threadIdx.y; i < 32; i += 8) {
        int k = k0 + i;
        const float* row = (k < R * D) ? (Wrel + (size_t)k * D)
                                       : (Wroot + (size_t)(k - R * D) * D);
        s[i][threadIdx.x] = row[j0 + threadIdx.x];
    }
    __syncthreads();
    for (int i = threadIdx.y; i < 32; i += 8) {
        int j = j0 + i;
        uint32_t u = f2tf(s[threadIdx.x][i]);
        ((uint32_t*)g_B)[(size_t)j * KTOT + k0 + threadIdx.x] = u;
    }
}

// ---------------- aggregate: warp per (node, rel); lazy-LN affine; tf32 out ----------------
__global__ __launch_bounds__(256) void aggregate(
    const float* __restrict__ x,
    const float* __restrict__ lnw, const float* __restrict__ lnb,
    const double* __restrict__ stats, int M, int Nn, int base)
{
    int wid = threadIdx.x >> 5, lane = threadIdx.x & 31;
    int seg = (base + blockIdx.x) * 8 + wid;
    int n = seg >> 3, r = seg & 7;
    int cnt = g_cnt[seg];
    int off = g_off[seg];
    float a[8] = {0, 0, 0, 0, 0, 0, 0, 0};
    for (int i = 0; i < cnt; i++) {
        int s = g_esrc[off + i];
        const float4* xp = (const float4*)(x + (size_t)s * D + lane * 8);
        float4 p0 = __ldg(xp), p1 = __ldg(xp + 1);
        a[0] += p0.x; a[1] += p0.y; a[2] += p0.z; a[3] += p0.w;
        a[4] += p1.x; a[5] += p1.y; a[6] += p1.z; a[7] += p1.w;
    }
    float sc = 1.0f / (float)max(cnt, 1);
    #pragma unroll
    for (int q = 0; q < 8; q++) a[q] *= sc;
    if (stats != nullptr && cnt > 0) {
        float mu, rs;
        ln_params(stats, M, mu, rs);
        #pragma unroll
        for (int q = 0; q < 8; q++) {
            int c = lane * 8 + q;
            a[q] = lnw[c] * ((a[q] - mu) * rs) + lnb[c];
        }
    }
    uint32_t w[8];
    #pragma unroll
    for (int q = 0; q < 8; q++) w[q] = f2tf(a[q]);
    uint32_t* o = (uint32_t*)g_A + (size_t)n * KTOT + r * D + lane * 8;
    *(uint4*)o       = make_uint4(w[0], w[1], w[2], w[3]);
    *(uint4*)(o + 4) = make_uint4(w[4], w[5], w[6], w[7]);
}

// ---------------- x -> tf32 into A cols [2048,2304); lazy-LN affine ----------------
__global__ void xconvert(const float* __restrict__ x,
                         const float* __restrict__ lnw, const float* __restrict__ lnb,
                         const double* __restrict__ stats, int M, int Nn)
{
    int idx = blockIdx.x * blockDim.x + threadIdx.x;
    int n = idx >> 5, c8 = (idx & 31) * 8;
    if (n >= NMAX) return;
    float v[8] = {0, 0, 0, 0, 0, 0, 0, 0};
    if (n < Nn) {
        float4 p0 = *(const float4*)(x + (size_t)n * D + c8);
        float4 p1 = *(const float4*)(x + (size_t)n * D + c8 + 4);
        v[0] = p0.x; v[1] = p0.y; v[2] = p0.z; v[3] = p0.w;
        v[4] = p1.x; v[5] = p1.y; v[6] = p1.z; v[7] = p1.w;
        if (stats != nullptr) {
            float mu, rs;
            ln_params(stats, M, mu, rs);
            #pragma unroll
            for (int q = 0; q < 8; q++)
                v[q] = lnw[c8 + q] * ((v[q] - mu) * rs) + lnb[c8 + q];
        }
    }
    uint32_t w[8];
    #pragma unroll
    for (int q = 0; q < 8; q++) w[q] = f2tf(v[q]);
    uint32_t* o = (uint32_t*)g_A + (size_t)n * KTOT + R * D + c8;
    *(uint4*)o       = make_uint4(w[0], w[1], w[2], w[3]);
    *(uint4*)(o + 4) = make_uint4(w[4], w[5], w[6], w[7]);
}

// ---------------- tf32 HMMA GEMM: 256 thr, 8 warps (64x64 tiles), 3-stage cp.async ----------------
__global__ __launch_bounds__(256) void rgcn_hmma(
    const float* __restrict__ Xcur,
    const float* __restrict__ bconv,
    float* __restrict__ Xnext, int Nn,
    const float* __restrict__ pw, const float* __restrict__ pb,
    const double* __restrict__ statsPrev,
    double* __restrict__ statsOut, int M)
{
    extern __shared__ char sm[];
    uint32_t sbase = smem_u32(sm);
    int tid = threadIdx.x, lane = tid & 31, wid = tid >> 5;
    int wm = wid & 1, wn = wid >> 1;            // rows wm*64, cols wn*64
    int row0 = blockIdx.x * BM;

    float acc[4][8][4];
    #pragma unroll
    for (int i = 0; i < 4; i++)
        #pragma unroll
        for (int j = 0; j < 8; j++)
            #pragma unroll
            for (int q = 0; q < 4; q++) acc[i][j][q] = 0.f;

    // cp.async mapping
    int arow = tid >> 1, ah = tid & 1;                        // A: 128 rows x 2 halves
    const float* gA = g_A + (size_t)(row0 + arow) * KTOT + ah * 16;
    uint32_t adst = (uint32_t)((arow * LDAf + ah * 16) * 4);
    const float* gB = g_B + (size_t)tid * KTOT;               // B: 256 rows, 1/thread
    uint32_t bdst = (uint32_t)(tid * LDAf * 4);

    auto issue = [&](int kt, int b) {
        uint32_t st = sbase + b * STG;
        int ko = kt * 32;
        cp16(st + OA + adst,      gA + ko);
        cp16(st + OA + adst + 16, gA + ko + 4);
        cp16(st + OA + adst + 32, gA + ko + 8);
        cp16(st + OA + adst + 48, gA + ko + 12);
        #pragma unroll
        for (int j = 0; j < 8; j++)
            cp16(st + OB + bdst + j * 16, gB + ko + j * 4);
    };

    issue(0, 0); cp_commit();
    issue(1, 1); cp_commit();
    issue(2, 2); cp_commit();

    int fr = lane >> 2, fc = lane & 3;

    #pragma unroll 1
    for (int kt = 0; kt < NST; kt++) {
        int b = kt % NSTAGE;
        cp_wait<NSTAGE - 1>();
        __syncthreads();

        const uint32_t* As = (const uint32_t*)(sm + b * STG + OA);
        const uint32_t* Bs = (const uint32_t*)(sm + b * STG + OB);

        #pragma unroll
        for (int kc = 0; kc < 4; kc++) {
            uint32_t a[4][4];
            #pragma unroll
            for (int mi = 0; mi < 4; mi++) {
                const uint32_t* Ab = As + (wm * 64 + mi * 16 + fr) * LDAf + kc * 8 + fc;
                a[mi][0] = Ab[0];
                a[mi][1] = Ab[8 * LDAf];
                a[mi][2] = Ab[4];
                a[mi][3] = Ab[8 * LDAf + 4];
            }
            #pragma unroll
            for (int nj = 0; nj < 8; nj++) {
                const uint32_t* Bb = Bs + (wn * 64 + nj * 8 + fr) * LDAf + kc * 8 + fc;
                uint32_t b0 = Bb[0], b1 = Bb[4];
                #pragma unroll
                for (int mi = 0; mi < 4; mi++)
                    mma_tf32(acc[mi][nj], a[mi], b0, b1);
            }
        }
        __syncthreads();
        if (kt + NSTAGE < NST) issue(kt + NSTAGE, b);
        cp_commit();
    }

    // ---- epilogue: bias + residual(affine) + relu + stats ----
    float mu = 0.f, rs = 0.f;
    bool ln = (statsPrev != nullptr);
    if (ln) ln_params(statsPrev, M, mu, rs);

    float ps = 0.f, pq = 0.f;
    #pragma unroll
    for (int mi = 0; mi < 4; mi++) {
        #pragma unroll
        for (int half = 0; half < 2; half++) {
            int n = row0 + wm * 64 + mi * 16 + fr + half * 8;
            if (n >= Nn) continue;
            #pragma unroll
            for (int nj = 0; nj < 8; nj++) {
                int col = wn * 64 + nj * 8 + fc * 2;
                float2 xv = *(const float2*)(Xcur + (size_t)n * D + col);
                float2 bv = *(const float2*)(bconv + col);
                if (ln) {
                    float2 wv = *(const float2*)(pw + col);
                    float2 bb = *(const float2*)(pb + col);
                    xv.x = wv.x * ((xv.x - mu) * rs) + bb.x;
                    xv.y = wv.y * ((xv.y - mu) * rs) + bb.y;
                }
                float2 o;
                o.x = fmaxf(acc[mi][nj][half * 2 + 0] + bv.x + xv.x, 0.f);
                o.y = fmaxf(acc[mi][nj][half * 2 + 1] + bv.y + xv.y, 0.f);
                *(float2*)(Xnext + (size_t)n * D + col) = o;
                ps += o.x + o.y;
                pq += o.x * o.x + o.y * o.y;
            }
        }
    }
    if (statsOut != nullptr) {
        #pragma unroll
        for (int o = 16; o > 0; o >>= 1) {
            ps += __shfl_down_sync(0xffffffffu, ps, o);
            pq += __shfl_down_sync(0xffffffffu, pq, o);
        }
        if (lane == 0) {
            atomicAdd(&statsOut[0], (double)ps);
            atomicAdd(&statsOut[1], (double)pq);
        }
    }
}

// ---------------- global mean pool + head ----------------
__global__ void pool_cnt(const int* __restrict__ batch, int Nn) {
    int i = blockIdx.x * blockDim.x + threadIdx.x;
    if (i < Nn) atomicAdd(&g_gcnt[batch[i]], 1);
}
__global__ void pool_sum(const float* __restrict__ X, const int* __restrict__ batch, int Nn) {
    int idx = blockIdx.x * blockDim.x + threadIdx.x;
    if (idx >= Nn * (D / 4)) return;
    int n = idx >> 6, c = idx & 63;
    float4 v = ((const float4*)X)[(size_t)n * (D / 4) + c];
    red_add_v4(g_pool + batch[n] * D + c * 4, v);
}
__global__ void head_kernel(const float* __restrict__ W1, const float* __restrict__ b1,
                            const float* __restrict__ W2, const float* __restrict__ b2,
                            const float* __restrict__ W3, const float* __restrict__ b3,
                            float* __restrict__ out) {
    __shared__ float g[D], h1[D], h2[D];
    int bg = blockIdx.x, j = threadIdx.x;
    float c = fmaxf((float)g_gcnt[bg], 1.f);
    g[j] = g_pool[bg * D + j] / c;
    __syncthreads();
    float acc = b1[j];
    for (int k = 0; k < D; k++) acc = fmaf(g[k], W1[k * D + j], acc);
    h1[j] = fmaxf(acc, 0.f);
    __syncthreads();
    acc = b2[j];
    for (int k = 0; k < D; k++) acc = fmaf(h1[k], W2[k * D + j], acc);
    h2[j] = fmaxf(acc, 0.f);
    __syncthreads();
    if (j < 4) {
        acc = b3[j];
        for (int k = 0; k < D; k++) acc = fmaf(h2[k], W3[k * 4 + j], acc);
        out[bg * 4 + j] = acc;
    }
}

// ---------------- launch ----------------
extern "C" void kernel_launch(void* const* d_in, const int* in_sizes, int n_in,
                              void* d_out, int out_size) {
    const float* x      = (const float*)d_in[0];
    const int*   ei     = (const int*)d_in[1];
    const int*   et     = (const int*)d_in[2];
    const int*   batch  = (const int*)d_in[3];
    const float* W_rel  = (const float*)d_in[4];
    const float* W_root = (const float*)d_in[5];
    const float* b_conv = (const float*)d_in[6];
    const float* ln_w   = (const float*)d_in[7];
    const float* ln_b   = (const float*)d_in[8];
    const float* W1 = (const float*)d_in[9];
    const float* b1 = (const float*)d_in[10];
    const float* W2 = (const float*)d_in[11];
    const float* b2 = (const float*)d_in[12];
    const float* W3 = (const float*)d_in[13];
    const float* b3 = (const float*)d_in[14];

    int E  = in_sizes[1] / 2;
    int Nn = in_sizes[0] / D;
    int M  = Nn * D;
    const int* src = ei;
    const int* dst = ei + E;
    int L = Nn * R;
    int nb = (L + 255) / 256;

    cudaFuncSetAttribute(rgcn_hmma, cudaFuncAttributeMaxDynamicSharedMemorySize, SMEM_TOTAL);

    void *pCnt, *pStats, *pPool, *pGcnt;
    cudaGetSymbolAddress(&pCnt, g_cnt);
    cudaGetSymbolAddress(&pStats, g_lnstats);
    cudaGetSymbolAddress(&pPool, g_pool);
    cudaGetSymbolAddress(&pGcnt, g_gcnt);
    double* pst = (double*)pStats;

    // launches: 1 memset, 2 count(+zero stats/cursor), 3 scan, 4 place,
    //           5/6 aggregate halves (ncu slot), 7 xconvert, 8 prep_B, 9 hmma, ...
    cudaMemsetAsync(pCnt, 0, (size_t)NMAX * R * sizeof(int));
    count_kernel<<<(E + 255) / 256, 256>>>(dst, et, E);
    scan_atomic<<<nb, 256>>>(L);
    place_kernel<<<(E + 255) / 256, 256>>>(src, dst, et, E);

    const float* cur = x;
    float* bufs[2];
    cudaGetSymbolAddress((void**)&bufs[0], g_X0);
    cudaGetSymbolAddress((void**)&bufs[1], g_X1);

    for (int l = 0; l < 3; l++) {
        const double* sp = (l > 0) ? (pst + (l - 1) * 2) : nullptr;
        const float* pw = (l > 0) ? (ln_w + (l - 1) * D) : nullptr;
        const float* pb = (l > 0) ? (ln_b + (l - 1) * D) : nullptr;
        if (l == 0) {
            aggregate<<<NMAX / 2, 256>>>(cur, pw, pb, sp, M, Nn, 0);
            aggregate<<<NMAX / 2, 256>>>(cur, pw, pb, sp, M, Nn, NMAX / 2);
        } else {
            aggregate<<<NMAX, 256>>>(cur, pw, pb, sp, M, Nn, 0);
        }
        xconvert<<<NMAX * 32 / 256, 256>>>(cur, pw, pb, sp, M, Nn);
        prep_B<<<dim3(KTOT / 32, D / 32), dim3(32, 8)>>>(
            W_rel + (size_t)l * R * D * D, W_root + (size_t)l * D * D);
        float* nxt = bufs[l & 1];
        double* so = (l < 2) ? (pst + l * 2) : nullptr;
        rgcn_hmma<<<NMAX / BM, 256, SMEM_TOTAL>>>(
            cur, b_conv + l * D, nxt, Nn, pw, pb, sp, so, M);
        cur = nxt;
    }

    cudaMemsetAsync(pPool, 0, NG * D * sizeof(float));
    cudaMemsetAsync(pGcnt, 0, NG * sizeof(int));
    pool_cnt<<<(Nn + 255) / 256, 256>>>(batch, Nn);
    pool_sum<<<(Nn * (D / 4) + 255) / 256, 256>>>(cur, batch, Nn);
    head_kernel<<<NG, D>>>(W1, b1, W2, b2, W3, b3, (float*)d_out);
}

// round 8
// speedup vs baseline: 2.3699x; 1.2852x over previous
#include <cuda_runtime.h>
#include <cuda_bf16.h>
#include <math.h>
#include <stdint.h>

#define D    256
#define R    8
#define NG   64
#define NMAX 50176          // 392*128
#define NBLK 392
#define EPS  1e-5f
#define KTOT 2304           // (R+1)*D
#define NST  72             // KTOT / 32
#define BM   128
#define EMAX 1048576

// padded tile geometry (floats)
#define LDAf  36
#define ATILE (128 * LDAf)              // 4608 floats = 18432 B
#define BTILE (256 * LDAf)              // 9216 floats = 36864 B
#define OA    0
#define OB    18432
#define STG   55296                     // bytes per stage
#define NSTAGE 3
#define SMEM_TOTAL (NSTAGE * STG + 64)  // + mbarriers

// ---------------- static device scratch ----------------
__device__ float  g_A[(size_t)NBLK * NST * ATILE];   // tile-major, tf32-rounded
__device__ float  g_B[(size_t)NST * BTILE];          // tile-major, tf32-rounded
__device__ float  g_X0[(size_t)NMAX * D];
__device__ float  g_X1[(size_t)NMAX * D];
__device__ int    g_cnt[NMAX * R];
__device__ int    g_off[NMAX * R];
__device__ int    g_pos[NMAX * R];
__device__ int    g_cursor[1];
__device__ int    g_esrc[EMAX];
__device__ double g_lnstats[3][2];
__device__ float  g_pool[NG * D];
__device__ int    g_gcnt[NG];

// ---------------- helpers ----------------
__device__ __forceinline__ uint32_t smem_u32(const void* p) {
    return (uint32_t)__cvta_generic_to_shared((void*)p);
}
__device__ __forceinline__ void red_add_v4(float* addr, float4 v) {
    asm volatile("red.global.add.v4.f32 [%0], {%1,%2,%3,%4};"
                 :: "l"(addr), "f"(v.x), "f"(v.y), "f"(v.z), "f"(v.w) : "memory");
}
__device__ __forceinline__ void mma_tf32(float (&d)[4], const uint32_t (&a)[4],
                                         uint32_t b0, uint32_t b1) {
    asm volatile(
        "mma.sync.aligned.m16n8k8.row.col.f32.tf32.tf32.f32 "
        "{%0,%1,%2,%3}, {%4,%5,%6,%7}, {%8,%9}, {%0,%1,%2,%3};"
        : "+f"(d[0]), "+f"(d[1]), "+f"(d[2]), "+f"(d[3])
        : "r"(a[0]), "r"(a[1]), "r"(a[2]), "r"(a[3]), "r"(b0), "r"(b1));
}
__device__ __forceinline__ uint32_t f2tf(float f) {
    uint32_t u;
    asm("cvt.rna.tf32.f32 %0, %1;" : "=r"(u) : "f"(f));
    return u;
}
__device__ __forceinline__ void mbar_init(uint32_t mb, uint32_t cnt) {
    asm volatile("mbarrier.init.shared.b64 [%0], %1;" :: "r"(mb), "r"(cnt) : "memory");
}
__device__ __forceinline__ void mbar_expect_tx(uint32_t mb, uint32_t bytes) {
    asm volatile("mbarrier.arrive.expect_tx.shared.b64 _, [%0], %1;"
                 :: "r"(mb), "r"(bytes) : "memory");
}
__device__ __forceinline__ void mbar_wait(uint32_t mb, uint32_t ph) {
    asm volatile(
        "{\n\t.reg .pred P;\n\t"
        "LW%=:\n\t"
        "mbarrier.try_wait.parity.acquire.cta.shared::cta.b64 P, [%0], %1, 0x989680;\n\t"
        "@P bra LD%=;\n\t"
        "bra LW%=;\n\t"
        "LD%=:\n\t}"
        :: "r"(mb), "r"(ph) : "memory");
}
__device__ __forceinline__ void bulk_g2s(uint32_t dst, const void* src,
                                         uint32_t bytes, uint32_t mb) {
    asm volatile(
        "cp.async.bulk.shared::cta.global.mbarrier::complete_tx::bytes [%0], [%1], %2, [%3];"
        :: "r"(dst), "l"(src), "r"(bytes), "r"(mb) : "memory");
}
__device__ __forceinline__ void ln_params(const double* st, int M, float& mu, float& rs) {
    double m = st[0] / (double)M;
    double var = st[1] / (double)M - m * m;
    mu = (float)m;
    rs = 1.0f / ((float)sqrt(fmax(var, 0.0)) + EPS);
}

// ---------------- CSR build ----------------
__global__ void count_kernel(const int* __restrict__ dst, const int* __restrict__ et, int E) {
    int i = blockIdx.x * blockDim.x + threadIdx.x;
    if (blockIdx.x == 0) {
        if (threadIdx.x < 6) ((double*)g_lnstats)[threadIdx.x] = 0.0;
        if (threadIdx.x == 6) g_cursor[0] = 0;
    }
    if (i < E) atomicAdd(&g_cnt[dst[i] * R + et[i]], 1);
}

__global__ void scan_atomic(int L) {
    __shared__ int sh[256];
    __shared__ int sbase;
    int tid = threadIdx.x;
    int i = blockIdx.x * 256 + tid;
    int v = (i < L) ? g_cnt[i] : 0;
    sh[tid] = v; __syncthreads();
    #pragma unroll
    for (int o = 1; o < 256; o <<= 1) {
        int t = (tid >= o) ? sh[tid - o] : 0;
        __syncthreads();
        sh[tid] += t;
        __syncthreads();
    }
    if (tid == 255) sbase = atomicAdd(&g_cursor[0], sh[255]);
    __syncthreads();
    if (i < L) {
        int o = sbase + sh[tid] - v;
        g_off[i] = o;
        g_pos[i] = o;
    }
}

__global__ void place_kernel(const int* __restrict__ src, const int* __restrict__ dst,
                             const int* __restrict__ et, int E) {
    int e = blockIdx.x * blockDim.x + threadIdx.x;
    if (e < E) {
        int seg = dst[e] * R + et[e];
        int p = atomicAdd(&g_pos[seg], 1);
        g_esrc[p] = src[e];
    }
}

// ---------------- weight prep: transpose + tf32 round into tiled layout ----------------
__global__ void prep_B(const float* __restrict__ Wrel, const float* __restrict__ Wroot) {
    __shared__ float s[32][33];
    int k0 = blockIdx.x * 32, j0 = blockIdx.y * 32;
    int kt = blockIdx.x;
    for (int i = threadIdx.y; i < 32; i += 8) {
        int k = k0 + i;
        const float* row = (k < R * D) ? (Wrel + (size_t)k * D)
                                       : (Wroot + (size_t)(k - R * D) * D);
        s[i][threadIdx.x] = row[j0 + threadIdx.x];
    }
    __syncthreads();
    for (int i = threadIdx.y; i < 32; i += 8) {
        int j = j0 + i;
        uint32_t u = f2tf(s[threadIdx.x][i]);
        ((uint32_t*)g_B)[(size_t)kt * BTILE + j * LDAf + threadIdx.x] = u;
    }
}

// ---------------- aggregate: warp per (node, rel); lazy-LN; tiled tf32 out ----------------
__global__ __launch_bounds__(256) void aggregate(
    const float* __restrict__ x,
    const float* __restrict__ lnw, const float* __restrict__ lnb,
    const double* __restrict__ stats, int M, int Nn)
{
    int wid = threadIdx.x >> 5, lane = threadIdx.x & 31;
    int seg = blockIdx.x * 8 + wid;            // 0 .. NMAX*R-1
    int n = seg >> 3, r = seg & 7;
    int cnt = g_cnt[seg];
    int off = g_off[seg];
    float a[8] = {0, 0, 0, 0, 0, 0, 0, 0};
    if (cnt > 0) {
        int s = __ldg(&g_esrc[off]);
        for (int i = 1; i < cnt; i++) {
            int sn = __ldg(&g_esrc[off + i]);          // prefetch next index
            const float4* xp = (const float4*)(x + (size_t)s * D + lane * 8);
            float4 p0 = __ldg(xp), p1 = __ldg(xp + 1);
            a[0] += p0.x; a[1] += p0.y; a[2] += p0.z; a[3] += p0.w;
            a[4] += p1.x; a[5] += p1.y; a[6] += p1.z; a[7] += p1.w;
            s = sn;
        }
        const float4* xp = (const float4*)(x + (size_t)s * D + lane * 8);
        float4 p0 = __ldg(xp), p1 = __ldg(xp + 1);
        a[0] += p0.x; a[1] += p0.y; a[2] += p0.z; a[3] += p0.w;
        a[4] += p1.x; a[5] += p1.y; a[6] += p1.z; a[7] += p1.w;

        float sc = 1.0f / (float)cnt;
        #pragma unroll
        for (int q = 0; q < 8; q++) a[q] *= sc;
        if (stats != nullptr) {
            float mu, rs;
            ln_params(stats, M, mu, rs);
            int c0 = lane * 8;                         // column within relation block
            #pragma unroll
            for (int q = 0; q < 8; q++)
                a[q] = lnw[c0 + q] * ((a[q] - mu) * rs) + lnb[c0 + q];
        }
    }
    uint32_t w[8];
    #pragma unroll
    for (int q = 0; q < 8; q++) w[q] = f2tf(a[q]);
    // tiled write: kt = r*8 + (lane>>2), col-in-tile (lane&3)*8, row = n & 127
    int blk = n >> 7, row = n & 127;
    int kt = r * 8 + (lane >> 2);
    uint32_t* o = (uint32_t*)g_A + ((size_t)blk * NST + kt) * ATILE
                + row * LDAf + (lane & 3) * 8;
    *(uint4*)o       = make_uint4(w[0], w[1], w[2], w[3]);
    *(uint4*)(o + 4) = make_uint4(w[4], w[5], w[6], w[7]);
}

// ---------------- x -> tf32 into A tiles kt 64..71; lazy-LN ----------------
__global__ void xconvert(const float* __restrict__ x,
                         const float* __restrict__ lnw, const float* __restrict__ lnb,
                         const double* __restrict__ stats, int M, int Nn)
{
    int idx = blockIdx.x * blockDim.x + threadIdx.x;
    int n = idx >> 5, c8 = (idx & 31) * 8;
    if (n >= NMAX) return;
    float v[8] = {0, 0, 0, 0, 0, 0, 0, 0};
    if (n < Nn) {
        float4 p0 = *(const float4*)(x + (size_t)n * D + c8);
        float4 p1 = *(const float4*)(x + (size_t)n * D + c8 + 4);
        v[0] = p0.x; v[1] = p0.y; v[2] = p0.z; v[3] = p0.w;
        v[4] = p1.x; v[5] = p1.y; v[6] = p1.z; v[7] = p1.w;
        if (stats != nullptr) {
            float mu, rs;
            ln_params(stats, M, mu, rs);
            #pragma unroll
            for (int q = 0; q < 8; q++)
                v[q] = lnw[c8 + q] * ((v[q] - mu) * rs) + lnb[c8 + q];
        }
    }
    uint32_t w[8];
    #pragma unroll
    for (int q = 0; q < 8; q++) w[q] = f2tf(v[q]);
    int blk = n >> 7, row = n & 127;
    int kt = 64 + (c8 >> 5);
    uint32_t* o = (uint32_t*)g_A + ((size_t)blk * NST + kt) * ATILE
                + row * LDAf + (c8 & 31);
    *(uint4*)o       = make_uint4(w[0], w[1], w[2], w[3]);
    *(uint4*)(o + 4) = make_uint4(w[4], w[5], w[6], w[7]);
}

// ---------------- tf32 GEMM: bulk-DMA stages, 8 warps 64x64, 3-stage ----------------
__global__ __launch_bounds__(256) void rgcn_hmma(
    const float* __restrict__ Xcur,
    const float* __restrict__ bconv,
    float* __restrict__ Xnext, int Nn,
    const float* __restrict__ pw, const float* __restrict__ pb,
    const double* __restrict__ statsPrev,
    double* __restrict__ statsOut, int M)
{
    extern __shared__ char sm[];
    uint32_t sbase = smem_u32(sm);
    uint32_t mbb = sbase + NSTAGE * STG;
    int tid = threadIdx.x, lane = tid & 31, wid = tid >> 5;
    int wm = wid & 1, wn = wid >> 1;
    int row0 = blockIdx.x * BM;
    const float* gAblk = g_A + (size_t)blockIdx.x * NST * ATILE;

    if (tid == 0) {
        #pragma unroll
        for (int s = 0; s < NSTAGE; s++) mbar_init(mbb + s * 8, 1);
    }
    __syncthreads();
    if (tid == 0) {
        #pragma unroll
        for (int s = 0; s < NSTAGE; s++) {
            mbar_expect_tx(mbb + s * 8, STG);
            bulk_g2s(sbase + s * STG + OA, gAblk + (size_t)s * ATILE, 18432, mbb + s * 8);
            bulk_g2s(sbase + s * STG + OB, g_B + (size_t)s * BTILE, 36864, mbb + s * 8);
        }
    }

    float acc[4][8][4];
    #pragma unroll
    for (int i = 0; i < 4; i++)
        #pragma unroll
        for (int j = 0; j < 8; j++)
            #pragma unroll
            for (int q = 0; q < 4; q++) acc[i][j][q] = 0.f;

    int fr = lane >> 2, fc = lane & 3;

    #pragma unroll 1
    for (int kt = 0; kt < NST; kt++) {
        int b = kt % NSTAGE;
        mbar_wait(mbb + b * 8, (kt / 3) & 1);

        const uint32_t* As = (const uint32_t*)(sm + b * STG + OA);
        const uint32_t* Bs = (const uint32_t*)(sm + b * STG + OB);

        #pragma unroll
        for (int kc = 0; kc < 4; kc++) {
            uint32_t a[4][4];
            #pragma unroll
            for (int mi = 0; mi < 4; mi++) {
                const uint32_t* Ab = As + (wm * 64 + mi * 16 + fr) * LDAf + kc * 8 + fc;
                a[mi][0] = Ab[0];
                a[mi][1] = Ab[8 * LDAf];
                a[mi][2] = Ab[4];
                a[mi][3] = Ab[8 * LDAf + 4];
            }
            #pragma unroll
            for (int nj = 0; nj < 8; nj++) {
                const uint32_t* Bb = Bs + (wn * 64 + nj * 8 + fr) * LDAf + kc * 8 + fc;
                uint32_t b0 = Bb[0], b1 = Bb[4];
                #pragma unroll
                for (int mi = 0; mi < 4; mi++)
                    mma_tf32(acc[mi][nj], a[mi], b0, b1);
            }
        }
        __syncthreads();
        if (tid == 0 && kt + NSTAGE < NST) {
            mbar_expect_tx(mbb + b * 8, STG);
            bulk_g2s(sbase + b * STG + OA, gAblk + (size_t)(kt + NSTAGE) * ATILE,
                     18432, mbb + b * 8);
            bulk_g2s(sbase + b * STG + OB, g_B + (size_t)(kt + NSTAGE) * BTILE,
                     36864, mbb + b * 8);
        }
    }

    // ---- epilogue: bias + residual(affine) + relu + stats ----
    float mu = 0.f, rs = 0.f;
    bool ln = (statsPrev != nullptr);
    if (ln) ln_params(statsPrev, M, mu, rs);

    float ps = 0.f, pq = 0.f;
    #pragma unroll
    for (int mi = 0; mi < 4; mi++) {
        #pragma unroll
        for (int half = 0; half < 2; half++) {
            int n = row0 + wm * 64 + mi * 16 + fr + half * 8;
            if (n >= Nn) continue;
            #pragma unroll
            for (int nj = 0; nj < 8; nj++) {
                int col = wn * 64 + nj * 8 + fc * 2;
                float2 xv = *(const float2*)(Xcur + (size_t)n * D + col);
                float2 bv = *(const float2*)(bconv + col);
                if (ln) {
                    float2 wv = *(const float2*)(pw + col);
                    float2 bb = *(const float2*)(pb + col);
                    xv.x = wv.x * ((xv.x - mu) * rs) + bb.x;
                    xv.y = wv.y * ((xv.y - mu) * rs) + bb.y;
                }
                float2 o;
                o.x = fmaxf(acc[mi][nj][half * 2 + 0] + bv.x + xv.x, 0.f);
                o.y = fmaxf(acc[mi][nj][half * 2 + 1] + bv.y + xv.y, 0.f);
                *(float2*)(Xnext + (size_t)n * D + col) = o;
                ps += o.x + o.y;
                pq += o.x * o.x + o.y * o.y;
            }
        }
    }
    if (statsOut != nullptr) {
        #pragma unroll
        for (int o = 16; o > 0; o >>= 1) {
            ps += __shfl_down_sync(0xffffffffu, ps, o);
            pq += __shfl_down_sync(0xffffffffu, pq, o);
        }
        if (lane == 0) {
            atomicAdd(&statsOut[0], (double)ps);
            atomicAdd(&statsOut[1], (double)pq);
        }
    }
}

// ---------------- global mean pool + head ----------------
__global__ void pool_cnt(const int* __restrict__ batch, int Nn) {
    int i = blockIdx.x * blockDim.x + threadIdx.x;
    if (i < Nn) atomicAdd(&g_gcnt[batch[i]], 1);
}
__global__ void pool_sum(const float* __restrict__ X, const int* __restrict__ batch, int Nn) {
    int idx = blockIdx.x * blockDim.x + threadIdx.x;
    if (idx >= Nn * (D / 4)) return;
    int n = idx >> 6, c = idx & 63;
    float4 v = ((const float4*)X)[(size_t)n * (D / 4) + c];
    red_add_v4(g_pool + batch[n] * D + c * 4, v);
}
__global__ void head_kernel(const float* __restrict__ W1, const float* __restrict__ b1,
                            const float* __restrict__ W2, const float* __restrict__ b2,
                            const float* __restrict__ W3, const float* __restrict__ b3,
                            float* __restrict__ out) {
    __shared__ float g[D], h1[D], h2[D];
    int bg = blockIdx.x, j = threadIdx.x;
    float c = fmaxf((float)g_gcnt[bg], 1.f);
    g[j] = g_pool[bg * D + j] / c;
    __syncthreads();
    float acc = b1[j];
    for (int k = 0; k < D; k++) acc = fmaf(g[k], W1[k * D + j], acc);
    h1[j] = fmaxf(acc, 0.f);
    __syncthreads();
    acc = b2[j];
    for (int k = 0; k < D; k++) acc = fmaf(h1[k], W2[k * D + j], acc);
    h2[j] = fmaxf(acc, 0.f);
    __syncthreads();
    if (j < 4) {
        acc = b3[j];
        for (int k = 0; k < D; k++) acc = fmaf(h2[k], W3[k * 4 + j], acc);
        out[bg * 4 + j] = acc;
    }
}

// ---------------- launch ----------------
extern "C" void kernel_launch(void* const* d_in, const int* in_sizes, int n_in,
                              void* d_out, int out_size) {
    const float* x      = (const float*)d_in[0];
    const int*   ei     = (const int*)d_in[1];
    const int*   et     = (const int*)d_in[2];
    const int*   batch  = (const int*)d_in[3];
    const float* W_rel  = (const float*)d_in[4];
    const float* W_root = (const float*)d_in[5];
    const float* b_conv = (const float*)d_in[6];
    const float* ln_w   = (const float*)d_in[7];
    const float* ln_b   = (const float*)d_in[8];
    const float* W1 = (const float*)d_in[9];
    const float* b1 = (const float*)d_in[10];
    const float* W2 = (const float*)d_in[11];
    const float* b2 = (const float*)d_in[12];
    const float* W3 = (const float*)d_in[13];
    const float* b3 = (const float*)d_in[14];

    int E  = in_sizes[1] / 2;
    int Nn = in_sizes[0] / D;
    int M  = Nn * D;
    const int* src = ei;
    const int* dst = ei + E;
    int L = Nn * R;
    int nb = (L + 255) / 256;

    cudaFuncSetAttribute(rgcn_hmma, cudaFuncAttributeMaxDynamicSharedMemorySize, SMEM_TOTAL);

    void *pCnt, *pStats, *pPool, *pGcnt;
    cudaGetSymbolAddress(&pCnt, g_cnt);
    cudaGetSymbolAddress(&pStats, g_lnstats);
    cudaGetSymbolAddress(&pPool, g_pool);
    cudaGetSymbolAddress(&pGcnt, g_gcnt);
    double* pst = (double*)pStats;

    cudaMemsetAsync(pCnt, 0, (size_t)NMAX * R * sizeof(int));
    count_kernel<<<(E + 255) / 256, 256>>>(dst, et, E);
    scan_atomic<<<nb, 256>>>(L);
    place_kernel<<<(E + 255) / 256, 256>>>(src, dst, et, E);

    const float* cur = x;
    float* bufs[2];
    cudaGetSymbolAddress((void**)&bufs[0], g_X0);
    cudaGetSymbolAddress((void**)&bufs[1], g_X1);

    for (int l = 0; l < 3; l++) {
        const double* sp = (l > 0) ? (pst + (l - 1) * 2) : nullptr;
        const float* pw = (l > 0) ? (ln_w + (l - 1) * D) : nullptr;
        const float* pb = (l > 0) ? (ln_b + (l - 1) * D) : nullptr;
        aggregate<<<NMAX, 256>>>(cur, pw, pb, sp, M, Nn);
        xconvert<<<NMAX * 32 / 256, 256>>>(cur, pw, pb, sp, M, Nn);
        prep_B<<<dim3(NST, D / 32), dim3(32, 8)>>>(
            W_rel + (size_t)l * R * D * D, W_root + (size_t)l * D * D);
        float* nxt = bufs[l & 1];
        double* so = (l < 2) ? (pst + l * 2) : nullptr;
        rgcn_hmma<<<NBLK, 256, SMEM_TOTAL>>>(
            cur, b_conv + l * D, nxt, Nn, pw, pb, sp, so, M);
        cur = nxt;
    }

    cudaMemsetAsync(pPool, 0, NG * D * sizeof(float));
    cudaMemsetAsync(pGcnt, 0, NG * sizeof(int));
    pool_cnt<<<(Nn + 255) / 256, 256>>>(batch, Nn);
    pool_sum<<<(Nn * (D / 4) + 255) / 256, 256>>>(cur, batch, Nn);
    head_kernel<<<NG, D>>>(W1, b1, W2, b2, W3, b3, (float*)d_out);
}